// round 2
// baseline (speedup 1.0000x reference)
#include <cuda_runtime.h>
#include <math.h>

// Problem constants
#define Bz 8
#define Sz 1024
#define Dz 512
#define Hz 8
#define DHz 64
#define FFz 2048
#define Lz 4
#define Nz (Bz*Sz)          // 8192 rows

// Scratch layout (floats) in one big device-global array
static constexpr size_t XBUF  = 0;
static constexpr size_t QBUF  = XBUF + (size_t)Nz*Dz;
static constexpr size_t KBUF  = QBUF + (size_t)Nz*Dz;
static constexpr size_t VBUF  = KBUF + (size_t)Nz*Dz;
static constexpr size_t ABUF  = VBUF + (size_t)Nz*Dz;
static constexpr size_t TBUF  = ABUF + (size_t)Nz*Dz;
static constexpr size_t YBUF  = TBUF + (size_t)Nz*Dz;
static constexpr size_t FBUF  = YBUF + (size_t)Nz*Dz;
static constexpr size_t SCBUF = FBUF + (size_t)Nz*FFz;
static constexpr size_t SCRATCH_TOTAL = SCBUF + (size_t)Bz*Hz*Sz*Sz;

__device__ float g_scratch[SCRATCH_TOTAL];

// ---------------------------------------------------------------------------
// Positional encoding: out = x + pe(s, d)
// ---------------------------------------------------------------------------
__global__ __launch_bounds__(256) void posenc_kernel(const float* __restrict__ x,
                                                     float* __restrict__ out) {
    int idx = blockIdx.x * 256 + threadIdx.x;      // over Nz*Dz
    int d = idx & (Dz - 1);
    int s = (idx >> 9) & (Sz - 1);
    int i2 = d & ~1;
    // div = exp(-(ln 10000 / D) * i2), computed in double then rounded
    float divv = (float)exp((double)i2 * (-9.210340371976184 / (double)Dz));
    float ang = (float)s * divv;
    float pe = (d & 1) ? cosf(ang) : sinf(ang);
    out[idx] = x[idx] + pe;
}

// ---------------------------------------------------------------------------
// GEMM: C[N,M] = A[N,K] @ W[K,M] + bias, optional ReLU
// BM=BN=128, BK=16, 256 threads, 8x8 per thread. Dims divisible (N=8192,
// K,M in {512,2048}).
// ---------------------------------------------------------------------------
template<bool RELU>
__global__ __launch_bounds__(256) void gemm_bias_kernel(
    const float* __restrict__ A, const float* __restrict__ W,
    const float* __restrict__ bias, float* __restrict__ C,
    int K, int M)
{
    __shared__ float As[16][128];   // [k][m]
    __shared__ float Ws[16][128];   // [k][n]
    int tid = threadIdx.x;
    int tx = tid & 15, ty = tid >> 4;
    int row0 = blockIdx.y * 128;
    int col0 = blockIdx.x * 128;
    float acc[8][8];
    #pragma unroll
    for (int i = 0; i < 8; i++)
        #pragma unroll
        for (int j = 0; j < 8; j++) acc[i][j] = 0.f;

    int ar  = tid >> 2;           // 0..63 (+64)
    int akc = (tid & 3) << 2;     // 0,4,8,12
    int wr  = tid >> 5;           // 0..7 (+8)
    int wc  = (tid & 31) << 2;    // 0..124

    for (int k0 = 0; k0 < K; k0 += 16) {
        #pragma unroll
        for (int i = 0; i < 2; i++) {
            int r = ar + i * 64;
            float4 av = *(const float4*)&A[(size_t)(row0 + r) * K + k0 + akc];
            As[akc + 0][r] = av.x; As[akc + 1][r] = av.y;
            As[akc + 2][r] = av.z; As[akc + 3][r] = av.w;
            int rw = wr + i * 8;
            float4 wv = *(const float4*)&W[(size_t)(k0 + rw) * M + col0 + wc];
            *(float4*)&Ws[rw][wc] = wv;
        }
        __syncthreads();
        #pragma unroll
        for (int kk = 0; kk < 16; kk++) {
            float ra[8], rb[8];
            *(float4*)&ra[0] = *(const float4*)&As[kk][ty * 8];
            *(float4*)&ra[4] = *(const float4*)&As[kk][ty * 8 + 4];
            *(float4*)&rb[0] = *(const float4*)&Ws[kk][tx * 8];
            *(float4*)&rb[4] = *(const float4*)&Ws[kk][tx * 8 + 4];
            #pragma unroll
            for (int i = 0; i < 8; i++)
                #pragma unroll
                for (int j = 0; j < 8; j++) acc[i][j] += ra[i] * rb[j];
        }
        __syncthreads();
    }

    float bb[8];
    *(float4*)&bb[0] = *(const float4*)&bias[col0 + tx * 8];
    *(float4*)&bb[4] = *(const float4*)&bias[col0 + tx * 8 + 4];
    #pragma unroll
    for (int i = 0; i < 8; i++) {
        int r = row0 + ty * 8 + i;
        float o[8];
        #pragma unroll
        for (int j = 0; j < 8; j++) {
            float v = acc[i][j] + bb[j];
            if (RELU) v = fmaxf(v, 0.f);
            o[j] = v;
        }
        *(float4*)&C[(size_t)r * M + col0 + tx * 8]     = *(float4*)&o[0];
        *(float4*)&C[(size_t)r * M + col0 + tx * 8 + 4] = *(float4*)&o[4];
    }
}

// ---------------------------------------------------------------------------
// QK^T: Sc[bh, q, k] = (1/8) * sum_d Q[b,q,h*64+d] * K[b,k,h*64+d]
// 128x128 tile per block, d-loop BK=16 (4 iters), 8x8 per thread
// ---------------------------------------------------------------------------
__global__ __launch_bounds__(256) void qk_kernel(
    const float* __restrict__ Q, const float* __restrict__ Kmat,
    float* __restrict__ Sc)
{
    __shared__ float Qs[16][128];   // [d][q]
    __shared__ float Ks[16][128];   // [d][k]
    int tid = threadIdx.x;
    int tx = tid & 15, ty = tid >> 4;
    int bh = blockIdx.z;
    int b = bh >> 3, h = bh & 7;
    int q0 = blockIdx.y * 128;
    int k0c = blockIdx.x * 128;
    const float* Qb = Q    + ((size_t)b * Sz + q0)  * Dz + h * DHz;
    const float* Kb = Kmat + ((size_t)b * Sz + k0c) * Dz + h * DHz;

    float acc[8][8];
    #pragma unroll
    for (int i = 0; i < 8; i++)
        #pragma unroll
        for (int j = 0; j < 8; j++) acc[i][j] = 0.f;

    int ar  = tid >> 2;
    int akc = (tid & 3) << 2;

    for (int d0 = 0; d0 < DHz; d0 += 16) {
        #pragma unroll
        for (int i = 0; i < 2; i++) {
            int r = ar + i * 64;
            float4 qv = *(const float4*)&Qb[(size_t)r * Dz + d0 + akc];
            Qs[akc + 0][r] = qv.x; Qs[akc + 1][r] = qv.y;
            Qs[akc + 2][r] = qv.z; Qs[akc + 3][r] = qv.w;
            float4 kv = *(const float4*)&Kb[(size_t)r * Dz + d0 + akc];
            Ks[akc + 0][r] = kv.x; Ks[akc + 1][r] = kv.y;
            Ks[akc + 2][r] = kv.z; Ks[akc + 3][r] = kv.w;
        }
        __syncthreads();
        #pragma unroll
        for (int kk = 0; kk < 16; kk++) {
            float ra[8], rb[8];
            *(float4*)&ra[0] = *(const float4*)&Qs[kk][ty * 8];
            *(float4*)&ra[4] = *(const float4*)&Qs[kk][ty * 8 + 4];
            *(float4*)&rb[0] = *(const float4*)&Ks[kk][tx * 8];
            *(float4*)&rb[4] = *(const float4*)&Ks[kk][tx * 8 + 4];
            #pragma unroll
            for (int i = 0; i < 8; i++)
                #pragma unroll
                for (int j = 0; j < 8; j++) acc[i][j] += ra[i] * rb[j];
        }
        __syncthreads();
    }

    #pragma unroll
    for (int i = 0; i < 8; i++) {
        float* out = Sc + ((size_t)bh * Sz + q0 + ty * 8 + i) * Sz + k0c + tx * 8;
        float o[8];
        #pragma unroll
        for (int j = 0; j < 8; j++) o[j] = acc[i][j] * 0.125f;
        *(float4*)&out[0] = *(float4*)&o[0];
        *(float4*)&out[4] = *(float4*)&o[4];
    }
}

// ---------------------------------------------------------------------------
// Masked softmax over rows of the score matrix. One block per (b,h,q) row.
// ---------------------------------------------------------------------------
__global__ __launch_bounds__(256) void softmax_kernel(float* __restrict__ Sc,
                                                      const int* __restrict__ lens)
{
    int row = blockIdx.x;                 // 0 .. B*H*S-1
    int b = row >> 13;                    // row / (H*S)
    int len = lens[b];
    float* p = Sc + (size_t)row * Sz;
    int tid = threadIdx.x;
    int lane = tid & 31, w = tid >> 5;
    __shared__ float sh[8];

    float v[4];
    float mx = -1e30f;
    #pragma unroll
    for (int i = 0; i < 4; i++) {
        int k = tid + (i << 8);
        v[i] = p[k];
        if (k < len && v[i] > mx) mx = v[i];
    }
    #pragma unroll
    for (int o = 16; o; o >>= 1) mx = fmaxf(mx, __shfl_xor_sync(0xffffffffu, mx, o));
    if (lane == 0) sh[w] = mx;
    __syncthreads();
    mx = sh[0];
    #pragma unroll
    for (int i = 1; i < 8; i++) mx = fmaxf(mx, sh[i]);
    __syncthreads();

    float sum = 0.f;
    #pragma unroll
    for (int i = 0; i < 4; i++) {
        int k = tid + (i << 8);
        float e = (k < len) ? __expf(v[i] - mx) : 0.f;
        v[i] = e;
        sum += e;
    }
    #pragma unroll
    for (int o = 16; o; o >>= 1) sum += __shfl_xor_sync(0xffffffffu, sum, o);
    if (lane == 0) sh[w] = sum;
    __syncthreads();
    float tot = 0.f;
    #pragma unroll
    for (int i = 0; i < 8; i++) tot += sh[i];
    float inv = 1.0f / tot;
    #pragma unroll
    for (int i = 0; i < 4; i++) p[tid + (i << 8)] = v[i] * inv;
}

// ---------------------------------------------------------------------------
// P @ V: O[b,q,h*64+c] = sum_k P[bh,q,k] * V[b,k,h*64+c]
// BM=128 (q), BN=64 (=DH), BK=16, 128 threads, 8x8 per thread
// ---------------------------------------------------------------------------
__global__ __launch_bounds__(128) void pv_kernel(
    const float* __restrict__ P, const float* __restrict__ V,
    float* __restrict__ O)
{
    __shared__ float Ps[16][128];   // [k][q]
    __shared__ float Vs[16][64];    // [k][dh]
    int tid = threadIdx.x;          // 0..127
    int tx = tid & 7, ty = tid >> 3;   // tx 0..7 (cols), ty 0..15 (rows)
    int bh = blockIdx.y;
    int b = bh >> 3, h = bh & 7;
    int q0 = blockIdx.x * 128;
    const float* Pb = P + ((size_t)bh * Sz + q0) * Sz;
    const float* Vb = V + (size_t)b * Sz * Dz + h * DHz;

    float acc[8][8];
    #pragma unroll
    for (int i = 0; i < 8; i++)
        #pragma unroll
        for (int j = 0; j < 8; j++) acc[i][j] = 0.f;

    for (int k0 = 0; k0 < Sz; k0 += 16) {
        #pragma unroll
        for (int i = 0; i < 4; i++) {
            int e = tid + i * 128;         // 0..511 float4 units
            int r = e >> 2;                // q row 0..127
            int kc = (e & 3) << 2;         // k 0,4,8,12
            float4 pv4 = *(const float4*)&Pb[(size_t)r * Sz + k0 + kc];
            Ps[kc + 0][r] = pv4.x; Ps[kc + 1][r] = pv4.y;
            Ps[kc + 2][r] = pv4.z; Ps[kc + 3][r] = pv4.w;
        }
        #pragma unroll
        for (int i = 0; i < 2; i++) {
            int e = tid + i * 128;         // 0..255 float4 units
            int vr = e >> 4;               // k row 0..15
            int vc = (e & 15) << 2;        // dh col 0..60
            float4 vv = *(const float4*)&Vb[(size_t)(k0 + vr) * Dz + vc];
            *(float4*)&Vs[vr][vc] = vv;
        }
        __syncthreads();
        #pragma unroll
        for (int kk = 0; kk < 16; kk++) {
            float ra[8], rb[8];
            *(float4*)&ra[0] = *(const float4*)&Ps[kk][ty * 8];
            *(float4*)&ra[4] = *(const float4*)&Ps[kk][ty * 8 + 4];
            *(float4*)&rb[0] = *(const float4*)&Vs[kk][tx * 8];
            *(float4*)&rb[4] = *(const float4*)&Vs[kk][tx * 8 + 4];
            #pragma unroll
            for (int i = 0; i < 8; i++)
                #pragma unroll
                for (int j = 0; j < 8; j++) acc[i][j] += ra[i] * rb[j];
        }
        __syncthreads();
    }

    #pragma unroll
    for (int i = 0; i < 8; i++) {
        float* out = O + ((size_t)b * Sz + q0 + ty * 8 + i) * Dz + h * DHz + tx * 8;
        *(float4*)&out[0] = *(float4*)&acc[i][0];
        *(float4*)&out[4] = *(float4*)&acc[i][4];
    }
}

// ---------------------------------------------------------------------------
// LayerNorm: out = g * (s - mean)/(sqrt(var_unbiased) + eps) + be,  s = Xa+Xb
// One block (256 threads) per row of D=512.
// ---------------------------------------------------------------------------
__global__ __launch_bounds__(256) void ln_kernel(
    const float* __restrict__ Xa, const float* __restrict__ Xb,
    const float* __restrict__ g, const float* __restrict__ be,
    float* __restrict__ out)
{
    int n = blockIdx.x;
    const float* a = Xa + (size_t)n * Dz;
    const float* c = Xb + (size_t)n * Dz;
    int tid = threadIdx.x;
    int lane = tid & 31, w = tid >> 5;
    __shared__ float sh[8];

    float s0 = a[tid] + c[tid];
    float s1 = a[tid + 256] + c[tid + 256];

    float sum = s0 + s1;
    #pragma unroll
    for (int o = 16; o; o >>= 1) sum += __shfl_xor_sync(0xffffffffu, sum, o);
    if (lane == 0) sh[w] = sum;
    __syncthreads();
    float tot = 0.f;
    #pragma unroll
    for (int i = 0; i < 8; i++) tot += sh[i];
    __syncthreads();
    float mean = tot * (1.0f / (float)Dz);

    float d0 = s0 - mean, d1 = s1 - mean;
    float ss = d0 * d0 + d1 * d1;
    #pragma unroll
    for (int o = 16; o; o >>= 1) ss += __shfl_xor_sync(0xffffffffu, ss, o);
    if (lane == 0) sh[w] = ss;
    __syncthreads();
    float tot2 = 0.f;
    #pragma unroll
    for (int i = 0; i < 8; i++) tot2 += sh[i];
    float var = tot2 * (1.0f / (float)(Dz - 1));
    float r = 1.0f / (sqrtf(var) + 1e-6f);

    out[(size_t)n * Dz + tid]       = g[tid]       * d0 * r + be[tid];
    out[(size_t)n * Dz + tid + 256] = g[tid + 256] * d1 * r + be[tid + 256];
}

// ---------------------------------------------------------------------------
// Host orchestration
// ---------------------------------------------------------------------------
extern "C" void kernel_launch(void* const* d_in, const int* in_sizes, int n_in,
                              void* d_out, int out_size)
{
    const float* x    = (const float*)d_in[0];
    const int*   lens = (const int*)  d_in[1];
    const float* Wq   = (const float*)d_in[2];
    const float* bq   = (const float*)d_in[3];
    const float* Wk   = (const float*)d_in[4];
    const float* bk   = (const float*)d_in[5];
    const float* Wv   = (const float*)d_in[6];
    const float* bv   = (const float*)d_in[7];
    const float* Wo   = (const float*)d_in[8];
    const float* bo   = (const float*)d_in[9];
    const float* W1   = (const float*)d_in[10];
    const float* b1   = (const float*)d_in[11];
    const float* W2   = (const float*)d_in[12];
    const float* b2   = (const float*)d_in[13];
    const float* g1   = (const float*)d_in[14];
    const float* be1  = (const float*)d_in[15];
    const float* g2   = (const float*)d_in[16];
    const float* be2  = (const float*)d_in[17];

    float* scratch = nullptr;
    cudaGetSymbolAddress((void**)&scratch, g_scratch);
    float* xb  = scratch + XBUF;
    float* qb  = scratch + QBUF;
    float* kb  = scratch + KBUF;
    float* vb  = scratch + VBUF;
    float* ab  = scratch + ABUF;
    float* tb  = scratch + TBUF;
    float* yb  = scratch + YBUF;
    float* fb  = scratch + FBUF;
    float* scb = scratch + SCBUF;

    posenc_kernel<<<(Nz * Dz) / 256, 256>>>(x, xb);

    dim3 gproj(Dz / 128, Nz / 128);   // (4, 64)
    dim3 gff1(FFz / 128, Nz / 128);   // (16, 64)

    for (int l = 0; l < Lz; l++) {
        const float* Wql = Wq + (size_t)l * Dz * Dz;
        const float* Wkl = Wk + (size_t)l * Dz * Dz;
        const float* Wvl = Wv + (size_t)l * Dz * Dz;
        const float* Wol = Wo + (size_t)l * Dz * Dz;
        const float* W1l = W1 + (size_t)l * Dz * FFz;
        const float* W2l = W2 + (size_t)l * FFz * Dz;
        const float* bql = bq + (size_t)l * Dz;
        const float* bkl = bk + (size_t)l * Dz;
        const float* bvl = bv + (size_t)l * Dz;
        const float* bol = bo + (size_t)l * Dz;
        const float* b1l = b1 + (size_t)l * FFz;
        const float* b2l = b2 + (size_t)l * Dz;
        const float* g1l = g1 + (size_t)l * Dz;
        const float* be1l= be1+ (size_t)l * Dz;
        const float* g2l = g2 + (size_t)l * Dz;
        const float* be2l= be2+ (size_t)l * Dz;

        gemm_bias_kernel<false><<<gproj, 256>>>(xb, Wql, bql, qb, Dz, Dz);
        gemm_bias_kernel<false><<<gproj, 256>>>(xb, Wkl, bkl, kb, Dz, Dz);
        gemm_bias_kernel<false><<<gproj, 256>>>(xb, Wvl, bvl, vb, Dz, Dz);

        qk_kernel<<<dim3(Sz / 128, Sz / 128, Bz * Hz), 256>>>(qb, kb, scb);
        softmax_kernel<<<Bz * Hz * Sz, 256>>>(scb, lens);
        pv_kernel<<<dim3(Sz / 128, Bz * Hz), 128>>>(scb, vb, ab);

        gemm_bias_kernel<false><<<gproj, 256>>>(ab, Wol, bol, tb, Dz, Dz);
        ln_kernel<<<Nz, 256>>>(xb, tb, g1l, be1l, yb);

        gemm_bias_kernel<true><<<gff1, 256>>>(yb, W1l, b1l, fb, Dz, FFz);
        gemm_bias_kernel<false><<<gproj, 256>>>(fb, W2l, b2l, tb, FFz, Dz);

        float* dst = (l == Lz - 1) ? (float*)d_out : xb;
        ln_kernel<<<Nz, 256>>>(yb, tb, g2l, be2l, dst);
    }
}

// round 4
// speedup vs baseline: 1.3376x; 1.3376x over previous
#include <cuda_runtime.h>
#include <cstdint>
#include <math.h>

#define Bz 8
#define Sz 1024
#define Dz 512
#define Hz 8
#define DHz 64
#define FFz 2048
#define Lz 4
#define Nz (Bz*Sz)

static constexpr size_t NB = (size_t)Nz*Dz;
static constexpr size_t FBsz = (size_t)Nz*FFz;
static constexpr size_t WPROJ = (size_t)Lz*Dz*Dz;
static constexpr size_t WFF = (size_t)Lz*Dz*FFz;

static constexpr size_t XBUF=0, QBUF=XBUF+NB, KBUF=QBUF+NB, VBUF=KBUF+NB,
  TBUF=VBUF+NB, YBUF=TBUF+NB, XHI=YBUF+NB, XLO=XHI+NB, ABHI=XLO+NB, ABLO=ABHI+NB,
  YHI=ABLO+NB, YLO=YHI+NB, FHI=YLO+NB, FLO=FHI+FBsz, SCBUF=FLO+FBsz,
  WQT=SCBUF+(size_t)Bz*Hz*Sz*Sz, WKT=WQT+2*WPROJ, WVT=WKT+2*WPROJ,
  WOT=WVT+2*WPROJ, W1T=WOT+2*WPROJ, W2T=W1T+2*WFF,
  SCRATCH_TOTAL=W2T+2*WFF;

__device__ float g_scratch[SCRATCH_TOTAL];

__device__ __forceinline__ uint32_t smem_u32(const void* p){ return (uint32_t)__cvta_generic_to_shared(p); }
__device__ __forceinline__ float to_tf32(float x){
  uint32_t u; asm("cvt.rna.tf32.f32 %0,%1;":"=r"(u):"f"(x)); return __uint_as_float(u); }

__device__ __forceinline__ void cp16(uint32_t d,const void* s){
  asm volatile("cp.async.cg.shared.global [%0],[%1],16;"::"r"(d),"l"(s):"memory"); }
#define CP_COMMIT() asm volatile("cp.async.commit_group;":::"memory")
#define CP_WAIT(n) asm volatile("cp.async.wait_group %0;"::"n"(n):"memory")

#define LDSM4(r,addr) asm volatile("ldmatrix.sync.aligned.m8n8.x4.shared.b16 {%0,%1,%2,%3},[%4];" \
  :"=r"((r)[0]),"=r"((r)[1]),"=r"((r)[2]),"=r"((r)[3]):"r"(addr))

#define MMA_TF32(c,a,b) asm volatile( \
  "mma.sync.aligned.m16n8k8.row.col.f32.tf32.tf32.f32 {%0,%1,%2,%3},{%4,%5,%6,%7},{%8,%9},{%0,%1,%2,%3};" \
  : "+f"((c)[0]),"+f"((c)[1]),"+f"((c)[2]),"+f"((c)[3]) \
  : "r"((a)[0]),"r"((a)[1]),"r"((a)[2]),"r"((a)[3]),"r"((b)[0]),"r"((b)[1]))

#define NSTG 3
#define STAGE_BYTES 65536
#define TILE_B 16384
static constexpr uint32_t GEMM_SMEM = NSTG*STAGE_BYTES;  // 192 KB

// C[N,M] = (Ahi+Alo)[N,K] @ (Bhi+Blo)[M,K]^T + bias
// MODE 0: write C fp32.  MODE 1: relu then write hi/lo split (Chi, Clo).
template<int MODE>
__global__ __launch_bounds__(256,1) void gemm_mma_kernel(
  const float* __restrict__ Ahi, const float* __restrict__ Alo,
  const float* __restrict__ Bhi, const float* __restrict__ Blo,
  const float* __restrict__ bias, float* __restrict__ C,
  float* __restrict__ Chi, float* __restrict__ Clo, int K, int M)
{
  extern __shared__ char smem[];
  const uint32_t sbase = smem_u32(smem);
  int tid=threadIdx.x, wid=tid>>5, lane=tid&31;
  int row0=blockIdx.y*128, col0=blockIdx.x*128;
  int rb=tid>>3, cb=(tid&7)<<2;
  const float* base[4] = { Ahi+(size_t)row0*K, Alo+(size_t)row0*K,
                           Bhi+(size_t)col0*K, Blo+(size_t)col0*K };
  int KT = K>>5;

  auto load_chunk=[&](int kt,int s){
    uint32_t sb = sbase + (uint32_t)s*STAGE_BYTES;
    int k0 = kt<<5;
    #pragma unroll
    for(int i=0;i<16;i++){
      int t4=i>>2;
      int r=((i&3)<<5)+rb;
      uint32_t bo=(uint32_t)(r*128+cb*4);
      cp16(sb+(uint32_t)(t4*TILE_B)+(bo^((bo>>3)&0x70)), base[t4]+(size_t)r*K+k0+cb);
    }
  };

  float acc[4][4][4];
  #pragma unroll
  for(int mt=0;mt<4;mt++)
    #pragma unroll
    for(int nt=0;nt<4;nt++)
      #pragma unroll
      for(int j=0;j<4;j++) acc[mt][nt][j]=0.f;

  // precompute per-thread fragment coordinates
  int wm = wid&1, wn = wid>>1;
  int mA = wm*64 + (lane&7) + ((lane>>3)&1)*8;   // + mt*16
  int kA = ((lane>>4)&1)*4;                       // + k0 per step
  int nB = wn*32 + (lane&7) + ((lane>>4)&1)*8;   // + bt*16
  int kB = ((lane>>3)&1)*4;

  #pragma unroll
  for(int p=0;p<NSTG-1;p++){ load_chunk(p,p); CP_COMMIT(); }

  for(int kt=0;kt<KT;kt++){
    int pre = kt+NSTG-1;
    if(pre<KT) load_chunk(pre, pre%NSTG);
    CP_COMMIT();
    CP_WAIT(NSTG-2);
    __syncthreads();
    uint32_t sb = sbase + (uint32_t)(kt%NSTG)*STAGE_BYTES;
    uint32_t sAh=sb, sAl=sb+TILE_B, sBh=sb+2*TILE_B, sBl=sb+3*TILE_B;
    #pragma unroll
    for(int st=0; st<4; st++){
      int k0 = st*8;
      uint32_t ah[16], al[16], bh[8], bl[8];
      #pragma unroll
      for(int mt=0;mt<4;mt++){
        int r = mA + mt*16;
        uint32_t off = (uint32_t)(r*128 + (((k0+kA)*4) ^ ((r&7)*16)));
        LDSM4(&ah[mt*4], sAh+off);
        LDSM4(&al[mt*4], sAl+off);
      }
      #pragma unroll
      for(int bt=0;bt<2;bt++){
        int n = nB + bt*16;
        uint32_t off = (uint32_t)(n*128 + (((k0+kB)*4) ^ ((n&7)*16)));
        LDSM4(&bh[bt*4], sBh+off);
        LDSM4(&bl[bt*4], sBl+off);
      }
      #pragma unroll
      for(int mt=0;mt<4;mt++){
        #pragma unroll
        for(int nt=0;nt<4;nt++){
          uint32_t* Bh2 = &bh[(nt>>1)*4 + (nt&1)*2];
          uint32_t* Bl2 = &bl[(nt>>1)*4 + (nt&1)*2];
          MMA_TF32(acc[mt][nt], &ah[mt*4], Bh2);
          MMA_TF32(acc[mt][nt], &ah[mt*4], Bl2);
          MMA_TF32(acc[mt][nt], &al[mt*4], Bh2);
        }
      }
    }
    __syncthreads();
  }

  // epilogue
  #pragma unroll
  for(int mt=0;mt<4;mt++){
    int r0 = row0 + wm*64 + mt*16 + (lane>>2);
    #pragma unroll
    for(int nt=0;nt<4;nt++){
      int c0i = col0 + wn*32 + nt*8 + 2*(lane&3);
      float b0v=bias[c0i], b1v=bias[c0i+1];
      float* a = acc[mt][nt];
      float v00=a[0]+b0v, v01=a[1]+b1v, v10=a[2]+b0v, v11=a[3]+b1v;
      if(MODE==0){
        *(float2*)&C[(size_t)r0*M + c0i]     = make_float2(v00,v01);
        *(float2*)&C[(size_t)(r0+8)*M + c0i] = make_float2(v10,v11);
      } else {
        v00=fmaxf(v00,0.f); v01=fmaxf(v01,0.f); v10=fmaxf(v10,0.f); v11=fmaxf(v11,0.f);
        float h00=to_tf32(v00), h01=to_tf32(v01), h10=to_tf32(v10), h11=to_tf32(v11);
        *(float2*)&Chi[(size_t)r0*M + c0i]     = make_float2(h00,h01);
        *(float2*)&Chi[(size_t)(r0+8)*M + c0i] = make_float2(h10,h11);
        *(float2*)&Clo[(size_t)r0*M + c0i]     = make_float2(to_tf32(v00-h00),to_tf32(v01-h01));
        *(float2*)&Clo[(size_t)(r0+8)*M + c0i] = make_float2(to_tf32(v10-h10),to_tf32(v11-h11));
      }
    }
  }
}

// W[K,M] (layer z) -> Wt hi/lo [M,K]
__global__ __launch_bounds__(256) void wsplit_kernel(
  const float* __restrict__ W, float* __restrict__ thi, float* __restrict__ tlo,
  int K, int M)
{
  __shared__ float t[32][33];
  int tx=threadIdx.x, ty=threadIdx.y;
  int m0=blockIdx.x*32, k0=blockIdx.y*32;
  size_t zo = (size_t)blockIdx.z*K*M;
  const float* Wz = W + zo;
  #pragma unroll
  for(int j=0;j<4;j++) t[ty+8*j][tx] = Wz[(size_t)(k0+ty+8*j)*M + m0+tx];
  __syncthreads();
  #pragma unroll
  for(int j=0;j<4;j++){
    float v = t[tx][ty+8*j];
    float h = to_tf32(v), l = to_tf32(v-h);
    size_t o = zo + (size_t)(m0+ty+8*j)*K + k0+tx;
    thi[o]=h; tlo[o]=l;
  }
}

__global__ __launch_bounds__(256) void posenc_kernel(const float* __restrict__ x,
  float* __restrict__ out, float* __restrict__ ohi, float* __restrict__ olo)
{
  int idx = blockIdx.x*256 + threadIdx.x;
  int d = idx & (Dz-1), s = (idx>>9) & (Sz-1);
  int i2 = d & ~1;
  float divv = (float)exp((double)i2 * (-9.210340371976184/(double)Dz));
  float ang = (float)s * divv;
  float pe = (d&1) ? cosf(ang) : sinf(ang);
  float v = x[idx] + pe;
  out[idx] = v;
  float h = to_tf32(v); ohi[idx]=h; olo[idx]=to_tf32(v-h);
}

__global__ __launch_bounds__(256) void qk_kernel(
  const float* __restrict__ Q, const float* __restrict__ Kmat, float* __restrict__ Sc)
{
  __shared__ float Qs[16][128];
  __shared__ float Ks[16][128];
  int tid=threadIdx.x, tx=tid&15, ty=tid>>4;
  int bh=blockIdx.z, b=bh>>3, h=bh&7;
  int q0=blockIdx.y*128, k0c=blockIdx.x*128;
  const float* Qb = Q + ((size_t)b*Sz+q0)*Dz + h*DHz;
  const float* Kb = Kmat + ((size_t)b*Sz+k0c)*Dz + h*DHz;
  float acc[8][8];
  #pragma unroll
  for(int i=0;i<8;i++){
    #pragma unroll
    for(int j=0;j<8;j++) acc[i][j]=0.f; }
  int ar=tid>>2, akc=(tid&3)<<2;
  for(int d0=0; d0<DHz; d0+=16){
    #pragma unroll
    for(int i=0;i<2;i++){
      int r=ar+i*64;
      float4 qv=*(const float4*)&Qb[(size_t)r*Dz+d0+akc];
      Qs[akc+0][r]=qv.x; Qs[akc+1][r]=qv.y; Qs[akc+2][r]=qv.z; Qs[akc+3][r]=qv.w;
      float4 kv=*(const float4*)&Kb[(size_t)r*Dz+d0+akc];
      Ks[akc+0][r]=kv.x; Ks[akc+1][r]=kv.y; Ks[akc+2][r]=kv.z; Ks[akc+3][r]=kv.w;
    }
    __syncthreads();
    #pragma unroll
    for(int kk=0;kk<16;kk++){
      float ra[8],rb[8];
      *(float4*)&ra[0]=*(const float4*)&Qs[kk][ty*8]; *(float4*)&ra[4]=*(const float4*)&Qs[kk][ty*8+4];
      *(float4*)&rb[0]=*(const float4*)&Ks[kk][tx*8]; *(float4*)&rb[4]=*(const float4*)&Ks[kk][tx*8+4];
      #pragma unroll
      for(int i=0;i<8;i++){
        #pragma unroll
        for(int j=0;j<8;j++) acc[i][j]+=ra[i]*rb[j]; }
    }
    __syncthreads();
  }
  #pragma unroll
  for(int i=0;i<8;i++){
    float* out = Sc + ((size_t)bh*Sz+q0+ty*8+i)*Sz + k0c + tx*8;
    float o[8];
    #pragma unroll
    for(int j=0;j<8;j++) o[j]=acc[i][j]*0.125f;
    *(float4*)&out[0]=*(float4*)&o[0]; *(float4*)&out[4]=*(float4*)&o[4];
  }
}

__global__ __launch_bounds__(256) void softmax_kernel(float* __restrict__ Sc,
                                                      const int* __restrict__ lens)
{
  int row=blockIdx.x, b=row>>13;
  int len=lens[b];
  float* p = Sc + (size_t)row*Sz;
  int tid=threadIdx.x, lane=tid&31, w=tid>>5;
  __shared__ float sh[8];
  float v[4]; float mx=-1e30f;
  #pragma unroll
  for(int i=0;i<4;i++){ int k=tid+(i<<8); v[i]=p[k]; if(k<len && v[i]>mx) mx=v[i]; }
  #pragma unroll
  for(int o=16;o;o>>=1) mx=fmaxf(mx,__shfl_xor_sync(0xffffffffu,mx,o));
  if(lane==0) sh[w]=mx;
  __syncthreads();
  mx=sh[0];
  #pragma unroll
  for(int i=1;i<8;i++) mx=fmaxf(mx,sh[i]);
  __syncthreads();
  float sum=0.f;
  #pragma unroll
  for(int i=0;i<4;i++){ int k=tid+(i<<8); float e=(k<len)?__expf(v[i]-mx):0.f; v[i]=e; sum+=e; }
  #pragma unroll
  for(int o=16;o;o>>=1) sum+=__shfl_xor_sync(0xffffffffu,sum,o);
  if(lane==0) sh[w]=sum;
  __syncthreads();
  float tot=0.f;
  #pragma unroll
  for(int i=0;i<8;i++) tot+=sh[i];
  float inv=1.0f/tot;
  #pragma unroll
  for(int i=0;i<4;i++) p[tid+(i<<8)]=v[i]*inv;
}

__global__ __launch_bounds__(128) void pv_kernel(
  const float* __restrict__ P, const float* __restrict__ V,
  float* __restrict__ Ohi, float* __restrict__ Olo)
{
  __shared__ float Ps[16][128];
  __shared__ float Vs[16][64];
  int tid=threadIdx.x, tx=tid&7, ty=tid>>3;
  int bh=blockIdx.y, b=bh>>3, h=bh&7;
  int q0=blockIdx.x*128;
  const float* Pb = P + ((size_t)bh*Sz+q0)*Sz;
  const float* Vb = V + (size_t)b*Sz*Dz + h*DHz;
  float acc[8][8];
  #pragma unroll
  for(int i=0;i<8;i++){
    #pragma unroll
    for(int j=0;j<8;j++) acc[i][j]=0.f; }
  for(int k0=0;k0<Sz;k0+=16){
    #pragma unroll
    for(int i=0;i<4;i++){
      int e=tid+i*128, r=e>>2, kc=(e&3)<<2;
      float4 p4=*(const float4*)&Pb[(size_t)r*Sz+k0+kc];
      Ps[kc+0][r]=p4.x; Ps[kc+1][r]=p4.y; Ps[kc+2][r]=p4.z; Ps[kc+3][r]=p4.w;
    }
    #pragma unroll
    for(int i=0;i<2;i++){
      int e=tid+i*128, vr=e>>4, vc=(e&15)<<2;
      *(float4*)&Vs[vr][vc] = *(const float4*)&Vb[(size_t)(k0+vr)*Dz+vc];
    }
    __syncthreads();
    #pragma unroll
    for(int kk=0;kk<16;kk++){
      float ra[8],rb[8];
      *(float4*)&ra[0]=*(const float4*)&Ps[kk][ty*8]; *(float4*)&ra[4]=*(const float4*)&Ps[kk][ty*8+4];
      *(float4*)&rb[0]=*(const float4*)&Vs[kk][tx*8]; *(float4*)&rb[4]=*(const float4*)&Vs[kk][tx*8+4];
      #pragma unroll
      for(int i=0;i<8;i++){
        #pragma unroll
        for(int j=0;j<8;j++) acc[i][j]+=ra[i]*rb[j]; }
    }
    __syncthreads();
  }
  #pragma unroll
  for(int i=0;i<8;i++){
    size_t o = ((size_t)b*Sz+q0+ty*8+i)*Dz + h*DHz + tx*8;
    float hi[8], lo[8];
    #pragma unroll
    for(int j=0;j<8;j++){ hi[j]=to_tf32(acc[i][j]); lo[j]=to_tf32(acc[i][j]-hi[j]); }
    *(float4*)&Ohi[o]=*(float4*)&hi[0]; *(float4*)&Ohi[o+4]=*(float4*)&hi[4];
    *(float4*)&Olo[o]=*(float4*)&lo[0]; *(float4*)&Olo[o+4]=*(float4*)&lo[4];
  }
}

template<bool SPLIT>
__global__ __launch_bounds__(256) void ln_kernel(
  const float* __restrict__ Xa, const float* __restrict__ Xb,
  const float* __restrict__ g, const float* __restrict__ be,
  float* __restrict__ out, float* __restrict__ ohi, float* __restrict__ olo)
{
  int n=blockIdx.x;
  const float* a = Xa + (size_t)n*Dz;
  const float* c = Xb + (size_t)n*Dz;
  int tid=threadIdx.x, lane=tid&31, w=tid>>5;
  __shared__ float sh[8];
  float s0=a[tid]+c[tid], s1=a[tid+256]+c[tid+256];
  float sum=s0+s1;
  #pragma unroll
  for(int o=16;o;o>>=1) sum+=__shfl_xor_sync(0xffffffffu,sum,o);
  if(lane==0) sh[w]=sum;
  __syncthreads();
  float tot=0.f;
  #pragma unroll
  for(int i=0;i<8;i++) tot+=sh[i];
  __syncthreads();
  float mean=tot*(1.0f/(float)Dz);
  float d0=s0-mean, d1=s1-mean;
  float ss=d0*d0+d1*d1;
  #pragma unroll
  for(int o=16;o;o>>=1) ss+=__shfl_xor_sync(0xffffffffu,ss,o);
  if(lane==0) sh[w]=ss;
  __syncthreads();
  float tot2=0.f;
  #pragma unroll
  for(int i=0;i<8;i++) tot2+=sh[i];
  float var=tot2*(1.0f/(float)(Dz-1));
  float r=1.0f/(sqrtf(var)+1e-6f);
  float v0=g[tid]*d0*r+be[tid];
  float v1=g[tid+256]*d1*r+be[tid+256];
  size_t o0=(size_t)n*Dz+tid, o1=o0+256;
  out[o0]=v0; out[o1]=v1;
  if (SPLIT){
    float h0=to_tf32(v0), h1=to_tf32(v1);
    ohi[o0]=h0; olo[o0]=to_tf32(v0-h0);
    ohi[o1]=h1; olo[o1]=to_tf32(v1-h1);
  }
}

extern "C" void kernel_launch(void* const* d_in, const int* in_sizes, int n_in,
                              void* d_out, int out_size)
{
  const float* x  =(const float*)d_in[0];
  const int* lens =(const int*)d_in[1];
  const float* Wq =(const float*)d_in[2];  const float* bq =(const float*)d_in[3];
  const float* Wk =(const float*)d_in[4];  const float* bk =(const float*)d_in[5];
  const float* Wv =(const float*)d_in[6];  const float* bv =(const float*)d_in[7];
  const float* Wo =(const float*)d_in[8];  const float* bo =(const float*)d_in[9];
  const float* W1 =(const float*)d_in[10]; const float* b1 =(const float*)d_in[11];
  const float* W2 =(const float*)d_in[12]; const float* b2 =(const float*)d_in[13];
  const float* g1 =(const float*)d_in[14]; const float* be1=(const float*)d_in[15];
  const float* g2 =(const float*)d_in[16]; const float* be2=(const float*)d_in[17];

  float* sc=nullptr;
  cudaGetSymbolAddress((void**)&sc, g_scratch);
  float *xb=sc+XBUF,*qb=sc+QBUF,*kb=sc+KBUF,*vb=sc+VBUF,*tb=sc+TBUF,*yb=sc+YBUF;
  float *xhi=sc+XHI,*xlo=sc+XLO,*abhi=sc+ABHI,*ablo=sc+ABLO;
  float *yhi=sc+YHI,*ylo=sc+YLO,*fhi=sc+FHI,*flo=sc+FLO,*scb=sc+SCBUF;
  float *wqt=sc+WQT,*wkt=sc+WKT,*wvt=sc+WVT,*wot=sc+WOT,*w1t=sc+W1T,*w2t=sc+W2T;

  cudaFuncSetAttribute(gemm_mma_kernel<0>, cudaFuncAttributeMaxDynamicSharedMemorySize, GEMM_SMEM);
  cudaFuncSetAttribute(gemm_mma_kernel<1>, cudaFuncAttributeMaxDynamicSharedMemorySize, GEMM_SMEM);

  dim3 wb(32,8);
  wsplit_kernel<<<dim3(Dz/32,Dz/32,Lz), wb>>>(Wq, wqt, wqt+WPROJ, Dz, Dz);
  wsplit_kernel<<<dim3(Dz/32,Dz/32,Lz), wb>>>(Wk, wkt, wkt+WPROJ, Dz, Dz);
  wsplit_kernel<<<dim3(Dz/32,Dz/32,Lz), wb>>>(Wv, wvt, wvt+WPROJ, Dz, Dz);
  wsplit_kernel<<<dim3(Dz/32,Dz/32,Lz), wb>>>(Wo, wot, wot+WPROJ, Dz, Dz);
  wsplit_kernel<<<dim3(FFz/32,Dz/32,Lz), wb>>>(W1, w1t, w1t+WFF, Dz, FFz);
  wsplit_kernel<<<dim3(Dz/32,FFz/32,Lz), wb>>>(W2, w2t, w2t+WFF, FFz, Dz);

  posenc_kernel<<<(Nz*Dz)/256, 256>>>(x, xb, xhi, xlo);

  dim3 gproj(Dz/128, Nz/128);     // (4,64)
  dim3 gff1(FFz/128, Nz/128);     // (16,64)

  for (int l=0;l<Lz;l++){
    size_t wp=(size_t)l*Dz*Dz, wf=(size_t)l*Dz*FFz;
    gemm_mma_kernel<0><<<gproj,256,GEMM_SMEM>>>(xhi,xlo, wqt+wp, wqt+WPROJ+wp, bq+l*Dz, qb,nullptr,nullptr, Dz,Dz);
    gemm_mma_kernel<0><<<gproj,256,GEMM_SMEM>>>(xhi,xlo, wkt+wp, wkt+WPROJ+wp, bk+l*Dz, kb,nullptr,nullptr, Dz,Dz);
    gemm_mma_kernel<0><<<gproj,256,GEMM_SMEM>>>(xhi,xlo, wvt+wp, wvt+WPROJ+wp, bv+l*Dz, vb,nullptr,nullptr, Dz,Dz);

    qk_kernel<<<dim3(Sz/128,Sz/128,Bz*Hz),256>>>(qb,kb,scb);
    softmax_kernel<<<Bz*Hz*Sz,256>>>(scb,lens);
    pv_kernel<<<dim3(Sz/128,Bz*Hz),128>>>(scb,vb,abhi,ablo);

    gemm_mma_kernel<0><<<gproj,256,GEMM_SMEM>>>(abhi,ablo, wot+wp, wot+WPROJ+wp, bo+l*Dz, tb,nullptr,nullptr, Dz,Dz);
    ln_kernel<true><<<Nz,256>>>(xb,tb,g1+l*Dz,be1+l*Dz, yb,yhi,ylo);

    gemm_mma_kernel<1><<<gff1,256,GEMM_SMEM>>>(yhi,ylo, w1t+wf, w1t+WFF+wf, b1+(size_t)l*FFz, nullptr,fhi,flo, Dz,FFz);
    gemm_mma_kernel<0><<<gproj,256,GEMM_SMEM>>>(fhi,flo, w2t+wf, w2t+WFF+wf, b2+l*Dz, tb,nullptr,nullptr, FFz,Dz);

    if (l==Lz-1)
      ln_kernel<false><<<Nz,256>>>(yb,tb,g2+l*Dz,be2+l*Dz,(float*)d_out,nullptr,nullptr);
    else
      ln_kernel<true><<<Nz,256>>>(yb,tb,g2+l*Dz,be2+l*Dz, xb,xhi,xlo);
  }
}

// round 5
// speedup vs baseline: 1.8323x; 1.3699x over previous
#include <cuda_runtime.h>
#include <cuda_bf16.h>
#include <cstdint>
#include <math.h>

#define Bz 8
#define Sz 1024
#define Dz 512
#define Hz 8
#define DHz 64
#define FFz 2048
#define Lz 4
#define Nz (Bz*Sz)

typedef __nv_bfloat16 bf;
typedef __nv_bfloat162 bf2;

static constexpr size_t NB = (size_t)Nz*Dz;
static constexpr size_t FBsz = (size_t)Nz*FFz;
static constexpr size_t WPROJ = (size_t)Lz*Dz*Dz;
static constexpr size_t WFF = (size_t)Lz*Dz*FFz;

// float offsets into scratch; bf16 buffers occupy half-float counts
static constexpr size_t XBUF=0, QBUF=XBUF+NB, KBUF=QBUF+NB, VBUF=KBUF+NB,
  TBUF=VBUF+NB, YBUF=TBUF+NB,
  XHI=YBUF+NB, XLO=XHI+NB/2, ABHI=XLO+NB/2, ABLO=ABHI+NB/2,
  YHI=ABLO+NB/2, YLO=YHI+NB/2, FHI=YLO+NB/2, FLO=FHI+FBsz/2,
  SCBUF=FLO+FBsz/2,
  WQT=SCBUF+(size_t)Bz*Hz*Sz*Sz, WKT=WQT+WPROJ, WVT=WKT+WPROJ,
  WOT=WVT+WPROJ, W1T=WOT+WPROJ, W2T=W1T+WFF,
  SCRATCH_TOTAL=W2T+WFF;

__device__ float g_scratch[SCRATCH_TOTAL];

__device__ __forceinline__ uint32_t smem_u32(const void* p){ return (uint32_t)__cvta_generic_to_shared(p); }
__device__ __forceinline__ void split_bf(float v, bf& h, bf& l){
  h = __float2bfloat16(v);
  l = __float2bfloat16(v - __bfloat162float(h));
}

__device__ __forceinline__ void cp16(uint32_t d,const void* s){
  asm volatile("cp.async.cg.shared.global [%0],[%1],16;"::"r"(d),"l"(s):"memory"); }
#define CP_COMMIT() asm volatile("cp.async.commit_group;":::"memory")
#define CP_WAIT(n) asm volatile("cp.async.wait_group %0;"::"n"(n):"memory")

#define LDSM4(r,addr) asm volatile("ldmatrix.sync.aligned.m8n8.x4.shared.b16 {%0,%1,%2,%3},[%4];" \
  :"=r"((r)[0]),"=r"((r)[1]),"=r"((r)[2]),"=r"((r)[3]):"r"(addr))

#define MMA_BF16(c,a,b) asm volatile( \
  "mma.sync.aligned.m16n8k16.row.col.f32.bf16.bf16.f32 {%0,%1,%2,%3},{%4,%5,%6,%7},{%8,%9},{%0,%1,%2,%3};" \
  : "+f"((c)[0]),"+f"((c)[1]),"+f"((c)[2]),"+f"((c)[3]) \
  : "r"((a)[0]),"r"((a)[1]),"r"((a)[2]),"r"((a)[3]),"r"((b)[0]),"r"((b)[1]))

#define NSTG 3
#define TILE_B 16384            // 128 rows x 128 bytes (64 bf16)
#define STAGE_BYTES 65536       // 4 tiles
static constexpr uint32_t GEMM_SMEM = NSTG*STAGE_BYTES;  // 192 KB

// C[N,M] = (Ahi+Alo)[N,K] @ (Bhi+Blo)[M,K]^T + bias.  K-chunk = 64.
// MODE 0: C fp32.  MODE 1: relu then bf16 hi/lo split to Chi/Clo.
template<int MODE>
__global__ __launch_bounds__(256,1) void gemm_mma_kernel(
  const bf* __restrict__ Ahi, const bf* __restrict__ Alo,
  const bf* __restrict__ Bhi, const bf* __restrict__ Blo,
  const float* __restrict__ bias, float* __restrict__ C,
  bf* __restrict__ Chi, bf* __restrict__ Clo, int K, int M)
{
  extern __shared__ char smem[];
  const uint32_t sbase = smem_u32(smem);
  int tid=threadIdx.x, wid=tid>>5, lane=tid&31;
  int row0=blockIdx.y*128, col0=blockIdx.x*128;
  int rb=tid>>3, c8=(tid&7);       // thread loads 16B = 8 bf16
  const bf* base[4] = { Ahi+(size_t)row0*K, Alo+(size_t)row0*K,
                        Bhi+(size_t)col0*K, Blo+(size_t)col0*K };
  int KT = K>>6;                   // chunks of 64

  auto load_chunk=[&](int kt,int s){
    uint32_t sb = sbase + (uint32_t)s*STAGE_BYTES;
    int k0e = kt<<6;
    #pragma unroll
    for(int i=0;i<16;i++){
      int t4=i>>2;
      int r=((i&3)<<5)+rb;
      uint32_t bo=(uint32_t)(r*128 + c8*16);
      cp16(sb+(uint32_t)(t4*TILE_B)+(bo^((bo>>3)&0x70)),
           base[t4]+(size_t)r*K+k0e+c8*8);
    }
  };

  float acc[4][4][4];
  #pragma unroll
  for(int mt=0;mt<4;mt++)
    #pragma unroll
    for(int nt=0;nt<4;nt++)
      #pragma unroll
      for(int j=0;j<4;j++) acc[mt][nt][j]=0.f;

  int wm = wid&1, wn = wid>>1;
  int mA = wm*64 + (lane&7) + ((lane>>3)&1)*8;     // + mt*16
  int kAby = ((lane>>4)&1)*16;                      // byte offset within k16 step
  int nB = wn*32 + (lane&7) + ((lane>>4)&1)*8;     // + bt*16
  int kBby = ((lane>>3)&1)*16;

  #pragma unroll
  for(int p=0;p<NSTG-1;p++){ load_chunk(p,p); CP_COMMIT(); }

  for(int kt=0;kt<KT;kt++){
    int pre = kt+NSTG-1;
    if(pre<KT) load_chunk(pre, pre%NSTG);
    CP_COMMIT();
    CP_WAIT(NSTG-2);
    __syncthreads();
    uint32_t sb = sbase + (uint32_t)(kt%NSTG)*STAGE_BYTES;
    uint32_t sAh=sb, sAl=sb+TILE_B, sBh=sb+2*TILE_B, sBl=sb+3*TILE_B;
    #pragma unroll
    for(int st=0; st<4; st++){
      int kby0 = st*32;          // 16 bf16 = 32 bytes per step
      uint32_t ah[16], al[16], bh[8], bl[8];
      #pragma unroll
      for(int mt=0;mt<4;mt++){
        int r = mA + mt*16;
        uint32_t off = (uint32_t)(r*128 + ((kby0+kAby) ^ ((r&7)*16)));
        LDSM4(&ah[mt*4], sAh+off);
        LDSM4(&al[mt*4], sAl+off);
      }
      #pragma unroll
      for(int bt=0;bt<2;bt++){
        int n = nB + bt*16;
        uint32_t off = (uint32_t)(n*128 + ((kby0+kBby) ^ ((n&7)*16)));
        LDSM4(&bh[bt*4], sBh+off);
        LDSM4(&bl[bt*4], sBl+off);
      }
      #pragma unroll
      for(int mt=0;mt<4;mt++){
        #pragma unroll
        for(int nt=0;nt<4;nt++){
          uint32_t* Bh2 = &bh[(nt>>1)*4 + (nt&1)*2];
          uint32_t* Bl2 = &bl[(nt>>1)*4 + (nt&1)*2];
          MMA_BF16(acc[mt][nt], &ah[mt*4], Bh2);
          MMA_BF16(acc[mt][nt], &ah[mt*4], Bl2);
          MMA_BF16(acc[mt][nt], &al[mt*4], Bh2);
        }
      }
    }
    __syncthreads();
  }

  #pragma unroll
  for(int mt=0;mt<4;mt++){
    int r0 = row0 + wm*64 + mt*16 + (lane>>2);
    #pragma unroll
    for(int nt=0;nt<4;nt++){
      int c0i = col0 + wn*32 + nt*8 + 2*(lane&3);
      float b0v=bias[c0i], b1v=bias[c0i+1];
      float* a = acc[mt][nt];
      float v00=a[0]+b0v, v01=a[1]+b1v, v10=a[2]+b0v, v11=a[3]+b1v;
      if(MODE==0){
        *(float2*)&C[(size_t)r0*M + c0i]     = make_float2(v00,v01);
        *(float2*)&C[(size_t)(r0+8)*M + c0i] = make_float2(v10,v11);
      } else {
        v00=fmaxf(v00,0.f); v01=fmaxf(v01,0.f); v10=fmaxf(v10,0.f); v11=fmaxf(v11,0.f);
        bf2 h0,l0,h1,l1;
        split_bf(v00,h0.x,l0.x); split_bf(v01,h0.y,l0.y);
        split_bf(v10,h1.x,l1.x); split_bf(v11,h1.y,l1.y);
        *(bf2*)&Chi[(size_t)r0*M + c0i]     = h0;
        *(bf2*)&Chi[(size_t)(r0+8)*M + c0i] = h1;
        *(bf2*)&Clo[(size_t)r0*M + c0i]     = l0;
        *(bf2*)&Clo[(size_t)(r0+8)*M + c0i] = l1;
      }
    }
  }
}

// W[K,M] (layer z via blockIdx.z) -> Wt hi/lo [M,K] bf16
__global__ __launch_bounds__(256) void wsplit_kernel(
  const float* __restrict__ W, bf* __restrict__ thi, bf* __restrict__ tlo,
  int K, int M)
{
  __shared__ float t[32][33];
  int tx=threadIdx.x, ty=threadIdx.y;
  int m0=blockIdx.x*32, k0=blockIdx.y*32;
  size_t zo = (size_t)blockIdx.z*K*M;
  const float* Wz = W + zo;
  #pragma unroll
  for(int j=0;j<4;j++) t[ty+8*j][tx] = Wz[(size_t)(k0+ty+8*j)*M + m0+tx];
  __syncthreads();
  #pragma unroll
  for(int j=0;j<4;j++){
    float v = t[tx][ty+8*j];
    bf h,l; split_bf(v,h,l);
    size_t o = zo + (size_t)(m0+ty+8*j)*K + k0+tx;
    thi[o]=h; tlo[o]=l;
  }
}

__global__ __launch_bounds__(256) void posenc_kernel(const float* __restrict__ x,
  float* __restrict__ out, bf* __restrict__ ohi, bf* __restrict__ olo)
{
  int idx = blockIdx.x*256 + threadIdx.x;
  int d = idx & (Dz-1), s = (idx>>9) & (Sz-1);
  int i2 = d & ~1;
  float divv = (float)exp((double)i2 * (-9.210340371976184/(double)Dz));
  float ang = (float)s * divv;
  float pe = (d&1) ? cosf(ang) : sinf(ang);
  float v = x[idx] + pe;
  out[idx] = v;
  bf h,l; split_bf(v,h,l);
  ohi[idx]=h; olo[idx]=l;
}

__global__ __launch_bounds__(256) void qk_kernel(
  const float* __restrict__ Q, const float* __restrict__ Kmat, float* __restrict__ Sc)
{
  __shared__ float Qs[16][128];
  __shared__ float Ks[16][128];
  int tid=threadIdx.x, tx=tid&15, ty=tid>>4;
  int bh=blockIdx.z, b=bh>>3, h=bh&7;
  int q0=blockIdx.y*128, k0c=blockIdx.x*128;
  const float* Qb = Q + ((size_t)b*Sz+q0)*Dz + h*DHz;
  const float* Kb = Kmat + ((size_t)b*Sz+k0c)*Dz + h*DHz;
  float acc[8][8];
  #pragma unroll
  for(int i=0;i<8;i++){
    #pragma unroll
    for(int j=0;j<8;j++) acc[i][j]=0.f; }
  int ar=tid>>2, akc=(tid&3)<<2;
  for(int d0=0; d0<DHz; d0+=16){
    #pragma unroll
    for(int i=0;i<2;i++){
      int r=ar+i*64;
      float4 qv=*(const float4*)&Qb[(size_t)r*Dz+d0+akc];
      Qs[akc+0][r]=qv.x; Qs[akc+1][r]=qv.y; Qs[akc+2][r]=qv.z; Qs[akc+3][r]=qv.w;
      float4 kv=*(const float4*)&Kb[(size_t)r*Dz+d0+akc];
      Ks[akc+0][r]=kv.x; Ks[akc+1][r]=kv.y; Ks[akc+2][r]=kv.z; Ks[akc+3][r]=kv.w;
    }
    __syncthreads();
    #pragma unroll
    for(int kk=0;kk<16;kk++){
      float ra[8],rb[8];
      *(float4*)&ra[0]=*(const float4*)&Qs[kk][ty*8]; *(float4*)&ra[4]=*(const float4*)&Qs[kk][ty*8+4];
      *(float4*)&rb[0]=*(const float4*)&Ks[kk][tx*8]; *(float4*)&rb[4]=*(const float4*)&Ks[kk][tx*8+4];
      #pragma unroll
      for(int i=0;i<8;i++){
        #pragma unroll
        for(int j=0;j<8;j++) acc[i][j]+=ra[i]*rb[j]; }
    }
    __syncthreads();
  }
  #pragma unroll
  for(int i=0;i<8;i++){
    float* out = Sc + ((size_t)bh*Sz+q0+ty*8+i)*Sz + k0c + tx*8;
    float o[8];
    #pragma unroll
    for(int j=0;j<8;j++) o[j]=acc[i][j]*0.125f;
    *(float4*)&out[0]=*(float4*)&o[0]; *(float4*)&out[4]=*(float4*)&o[4];
  }
}

__global__ __launch_bounds__(256) void softmax_kernel(float* __restrict__ Sc,
                                                      const int* __restrict__ lens)
{
  int row=blockIdx.x, b=row>>13;
  int len=lens[b];
  float* p = Sc + (size_t)row*Sz;
  int tid=threadIdx.x, lane=tid&31, w=tid>>5;
  __shared__ float sh[8];
  float v[4]; float mx=-1e30f;
  #pragma unroll
  for(int i=0;i<4;i++){ int k=tid+(i<<8); v[i]=p[k]; if(k<len && v[i]>mx) mx=v[i]; }
  #pragma unroll
  for(int o=16;o;o>>=1) mx=fmaxf(mx,__shfl_xor_sync(0xffffffffu,mx,o));
  if(lane==0) sh[w]=mx;
  __syncthreads();
  mx=sh[0];
  #pragma unroll
  for(int i=1;i<8;i++) mx=fmaxf(mx,sh[i]);
  __syncthreads();
  float sum=0.f;
  #pragma unroll
  for(int i=0;i<4;i++){ int k=tid+(i<<8); float e=(k<len)?__expf(v[i]-mx):0.f; v[i]=e; sum+=e; }
  #pragma unroll
  for(int o=16;o;o>>=1) sum+=__shfl_xor_sync(0xffffffffu,sum,o);
  if(lane==0) sh[w]=sum;
  __syncthreads();
  float tot=0.f;
  #pragma unroll
  for(int i=0;i<8;i++) tot+=sh[i];
  float inv=1.0f/tot;
  #pragma unroll
  for(int i=0;i<4;i++) p[tid+(i<<8)]=v[i]*inv;
}

__global__ __launch_bounds__(128) void pv_kernel(
  const float* __restrict__ P, const float* __restrict__ V,
  bf* __restrict__ Ohi, bf* __restrict__ Olo)
{
  __shared__ float Ps[16][128];
  __shared__ float Vs[16][64];
  int tid=threadIdx.x, tx=tid&7, ty=tid>>3;
  int bh=blockIdx.y, b=bh>>3, h=bh&7;
  int q0=blockIdx.x*128;
  const float* Pb = P + ((size_t)bh*Sz+q0)*Sz;
  const float* Vb = V + (size_t)b*Sz*Dz + h*DHz;
  float acc[8][8];
  #pragma unroll
  for(int i=0;i<8;i++){
    #pragma unroll
    for(int j=0;j<8;j++) acc[i][j]=0.f; }
  for(int k0=0;k0<Sz;k0+=16){
    #pragma unroll
    for(int i=0;i<4;i++){
      int e=tid+i*128, r=e>>2, kc=(e&3)<<2;
      float4 p4=*(const float4*)&Pb[(size_t)r*Sz+k0+kc];
      Ps[kc+0][r]=p4.x; Ps[kc+1][r]=p4.y; Ps[kc+2][r]=p4.z; Ps[kc+3][r]=p4.w;
    }
    #pragma unroll
    for(int i=0;i<2;i++){
      int e=tid+i*128, vr=e>>4, vc=(e&15)<<2;
      *(float4*)&Vs[vr][vc] = *(const float4*)&Vb[(size_t)(k0+vr)*Dz+vc];
    }
    __syncthreads();
    #pragma unroll
    for(int kk=0;kk<16;kk++){
      float ra[8],rb[8];
      *(float4*)&ra[0]=*(const float4*)&Ps[kk][ty*8]; *(float4*)&ra[4]=*(const float4*)&Ps[kk][ty*8+4];
      *(float4*)&rb[0]=*(const float4*)&Vs[kk][tx*8]; *(float4*)&rb[4]=*(const float4*)&Vs[kk][tx*8+4];
      #pragma unroll
      for(int i=0;i<8;i++){
        #pragma unroll
        for(int j=0;j<8;j++) acc[i][j]+=ra[i]*rb[j]; }
    }
    __syncthreads();
  }
  #pragma unroll
  for(int i=0;i<8;i++){
    size_t o = ((size_t)b*Sz+q0+ty*8+i)*Dz + h*DHz + tx*8;
    #pragma unroll
    for(int j=0;j<8;j+=2){
      bf2 h2,l2;
      split_bf(acc[i][j],  h2.x, l2.x);
      split_bf(acc[i][j+1],h2.y, l2.y);
      *(bf2*)&Ohi[o+j]=h2;
      *(bf2*)&Olo[o+j]=l2;
    }
  }
}

template<bool SPLIT>
__global__ __launch_bounds__(256) void ln_kernel(
  const float* __restrict__ Xa, const float* __restrict__ Xb,
  const float* __restrict__ g, const float* __restrict__ be,
  float* __restrict__ out, bf* __restrict__ ohi, bf* __restrict__ olo)
{
  int n=blockIdx.x;
  const float* a = Xa + (size_t)n*Dz;
  const float* c = Xb + (size_t)n*Dz;
  int tid=threadIdx.x, lane=tid&31, w=tid>>5;
  __shared__ float sh[8];
  float s0=a[tid]+c[tid], s1=a[tid+256]+c[tid+256];
  float sum=s0+s1;
  #pragma unroll
  for(int o=16;o;o>>=1) sum+=__shfl_xor_sync(0xffffffffu,sum,o);
  if(lane==0) sh[w]=sum;
  __syncthreads();
  float tot=0.f;
  #pragma unroll
  for(int i=0;i<8;i++) tot+=sh[i];
  __syncthreads();
  float mean=tot*(1.0f/(float)Dz);
  float d0=s0-mean, d1=s1-mean;
  float ss=d0*d0+d1*d1;
  #pragma unroll
  for(int o=16;o;o>>=1) ss+=__shfl_xor_sync(0xffffffffu,ss,o);
  if(lane==0) sh[w]=ss;
  __syncthreads();
  float tot2=0.f;
  #pragma unroll
  for(int i=0;i<8;i++) tot2+=sh[i];
  float var=tot2*(1.0f/(float)(Dz-1));
  float r=1.0f/(sqrtf(var)+1e-6f);
  float v0=g[tid]*d0*r+be[tid];
  float v1=g[tid+256]*d1*r+be[tid+256];
  size_t o0=(size_t)n*Dz+tid, o1=o0+256;
  out[o0]=v0; out[o1]=v1;
  if (SPLIT){
    bf h,l;
    split_bf(v0,h,l); ohi[o0]=h; olo[o0]=l;
    split_bf(v1,h,l); ohi[o1]=h; olo[o1]=l;
  }
}

extern "C" void kernel_launch(void* const* d_in, const int* in_sizes, int n_in,
                              void* d_out, int out_size)
{
  const float* x  =(const float*)d_in[0];
  const int* lens =(const int*)d_in[1];
  const float* Wq =(const float*)d_in[2];  const float* bq =(const float*)d_in[3];
  const float* Wk =(const float*)d_in[4];  const float* bk =(const float*)d_in[5];
  const float* Wv =(const float*)d_in[6];  const float* bv =(const float*)d_in[7];
  const float* Wo =(const float*)d_in[8];  const float* bo =(const float*)d_in[9];
  const float* W1 =(const float*)d_in[10]; const float* b1 =(const float*)d_in[11];
  const float* W2 =(const float*)d_in[12]; const float* b2 =(const float*)d_in[13];
  const float* g1 =(const float*)d_in[14]; const float* be1=(const float*)d_in[15];
  const float* g2 =(const float*)d_in[16]; const float* be2=(const float*)d_in[17];

  float* sc=nullptr;
  cudaGetSymbolAddress((void**)&sc, g_scratch);
  float *xb=sc+XBUF,*qb=sc+QBUF,*kb=sc+KBUF,*vb=sc+VBUF,*tb=sc+TBUF,*yb=sc+YBUF,*scb=sc+SCBUF;
  bf *xhi=(bf*)(sc+XHI), *xlo=(bf*)(sc+XLO);
  bf *abhi=(bf*)(sc+ABHI), *ablo=(bf*)(sc+ABLO);
  bf *yhi=(bf*)(sc+YHI), *ylo=(bf*)(sc+YLO);
  bf *fhi=(bf*)(sc+FHI), *flo=(bf*)(sc+FLO);
  bf *wqh=(bf*)(sc+WQT), *wql=wqh+WPROJ;
  bf *wkh=(bf*)(sc+WKT), *wkl=wkh+WPROJ;
  bf *wvh=(bf*)(sc+WVT), *wvl=wvh+WPROJ;
  bf *woh=(bf*)(sc+WOT), *wol=woh+WPROJ;
  bf *w1h=(bf*)(sc+W1T), *w1l=w1h+WFF;
  bf *w2h=(bf*)(sc+W2T), *w2l=w2h+WFF;

  cudaFuncSetAttribute(gemm_mma_kernel<0>, cudaFuncAttributeMaxDynamicSharedMemorySize, GEMM_SMEM);
  cudaFuncSetAttribute(gemm_mma_kernel<1>, cudaFuncAttributeMaxDynamicSharedMemorySize, GEMM_SMEM);

  dim3 wb(32,8);
  wsplit_kernel<<<dim3(Dz/32,Dz/32,Lz), wb>>>(Wq, wqh, wql, Dz, Dz);
  wsplit_kernel<<<dim3(Dz/32,Dz/32,Lz), wb>>>(Wk, wkh, wkl, Dz, Dz);
  wsplit_kernel<<<dim3(Dz/32,Dz/32,Lz), wb>>>(Wv, wvh, wvl, Dz, Dz);
  wsplit_kernel<<<dim3(Dz/32,Dz/32,Lz), wb>>>(Wo, woh, wol, Dz, Dz);
  wsplit_kernel<<<dim3(FFz/32,Dz/32,Lz), wb>>>(W1, w1h, w1l, Dz, FFz);
  wsplit_kernel<<<dim3(Dz/32,FFz/32,Lz), wb>>>(W2, w2h, w2l, FFz, Dz);

  posenc_kernel<<<(Nz*Dz)/256, 256>>>(x, xb, xhi, xlo);

  dim3 gproj(Dz/128, Nz/128);     // (4,64)
  dim3 gff1(FFz/128, Nz/128);     // (16,64)

  for (int l=0;l<Lz;l++){
    size_t wp=(size_t)l*Dz*Dz, wf=(size_t)l*Dz*FFz;
    gemm_mma_kernel<0><<<gproj,256,GEMM_SMEM>>>(xhi,xlo, wqh+wp,wql+wp, bq+l*Dz, qb,nullptr,nullptr, Dz,Dz);
    gemm_mma_kernel<0><<<gproj,256,GEMM_SMEM>>>(xhi,xlo, wkh+wp,wkl+wp, bk+l*Dz, kb,nullptr,nullptr, Dz,Dz);
    gemm_mma_kernel<0><<<gproj,256,GEMM_SMEM>>>(xhi,xlo, wvh+wp,wvl+wp, bv+l*Dz, vb,nullptr,nullptr, Dz,Dz);

    qk_kernel<<<dim3(Sz/128,Sz/128,Bz*Hz),256>>>(qb,kb,scb);
    softmax_kernel<<<Bz*Hz*Sz,256>>>(scb,lens);
    pv_kernel<<<dim3(Sz/128,Bz*Hz),128>>>(scb,vb,abhi,ablo);

    gemm_mma_kernel<0><<<gproj,256,GEMM_SMEM>>>(abhi,ablo, woh+wp,wol+wp, bo+l*Dz, tb,nullptr,nullptr, Dz,Dz);
    ln_kernel<true><<<Nz,256>>>(xb,tb,g1+l*Dz,be1+l*Dz, yb,yhi,ylo);

    gemm_mma_kernel<1><<<gff1,256,GEMM_SMEM>>>(yhi,ylo, w1h+wf,w1l+wf, b1+(size_t)l*FFz, nullptr,fhi,flo, Dz,FFz);
    gemm_mma_kernel<0><<<gproj,256,GEMM_SMEM>>>(fhi,flo, w2h+wf,w2l+wf, b2+l*Dz, tb,nullptr,nullptr, FFz,Dz);

    if (l==Lz-1)
      ln_kernel<false><<<Nz,256>>>(yb,tb,g2+l*Dz,be2+l*Dz,(float*)d_out,nullptr,nullptr);
    else
      ln_kernel<true><<<Nz,256>>>(yb,tb,g2+l*Dz,be2+l*Dz, xb,xhi,xlo);
  }
}

// round 6
// speedup vs baseline: 3.1165x; 1.7009x over previous
#include <cuda_runtime.h>
#include <cuda_bf16.h>
#include <cstdint>
#include <math.h>

#define Bz 8
#define Sz 1024
#define Dz 512
#define Hz 8
#define DHz 64
#define FFz 2048
#define Lz 4
#define Nz (Bz*Sz)

typedef __nv_bfloat16 bf;
typedef __nv_bfloat162 bf2;

static constexpr size_t NB = (size_t)Nz*Dz;
static constexpr size_t FBsz = (size_t)Nz*FFz;
static constexpr size_t WPROJ = (size_t)Lz*Dz*Dz;
static constexpr size_t WFF = (size_t)Lz*Dz*FFz;

// float-unit offsets; bf16 buffers take NB/2 floats
static constexpr size_t XBUF=0, TBUF=NB, YBUF=2*NB,
  QHIo=3*NB, QLOo=QHIo+NB/2, KHIo=QLOo+NB/2, KLOo=KHIo+NB/2,
  VTHIo=KLOo+NB/2, VTLOo=VTHIo+NB/2, ABHIo=VTLOo+NB/2, ABLOo=ABHIo+NB/2,
  XHIo=ABLOo+NB/2, XLOo=XHIo+NB/2, YHIo=XLOo+NB/2, YLOo=YHIo+NB/2,
  FHIo=YLOo+NB/2, FLOo=FHIo+FBsz/2,
  WQo=FLOo+FBsz/2, WKo=WQo+WPROJ, WVo=WKo+WPROJ, WOo=WVo+WPROJ,
  W1o=WOo+WPROJ, W2o=W1o+WFF, SCRATCH_TOTAL=W2o+WFF;

__device__ float g_scratch[SCRATCH_TOTAL];

__device__ __forceinline__ uint32_t smem_u32(const void* p){ return (uint32_t)__cvta_generic_to_shared(p); }
__device__ __forceinline__ void split_bf(float v, bf& h, bf& l){
  h = __float2bfloat16(v);
  l = __float2bfloat16(v - __bfloat162float(h));
}
__device__ __forceinline__ uint32_t pack2(bf a, bf b){
  bf2 t; t.x=a; t.y=b; uint32_t r; memcpy(&r,&t,4); return r; }

__device__ __forceinline__ void cp16(uint32_t d,const void* s){
  asm volatile("cp.async.cg.shared.global [%0],[%1],16;"::"r"(d),"l"(s):"memory"); }
#define CP_COMMIT() asm volatile("cp.async.commit_group;":::"memory")
#define CP_WAIT(n) asm volatile("cp.async.wait_group %0;"::"n"(n):"memory")

#define LDSM4(r,addr) asm volatile("ldmatrix.sync.aligned.m8n8.x4.shared.b16 {%0,%1,%2,%3},[%4];" \
  :"=r"((r)[0]),"=r"((r)[1]),"=r"((r)[2]),"=r"((r)[3]):"r"(addr))

#define MMA_BF16(c,a,b) asm volatile( \
  "mma.sync.aligned.m16n8k16.row.col.f32.bf16.bf16.f32 {%0,%1,%2,%3},{%4,%5,%6,%7},{%8,%9},{%0,%1,%2,%3};" \
  : "+f"((c)[0]),"+f"((c)[1]),"+f"((c)[2]),"+f"((c)[3]) \
  : "r"((a)[0]),"r"((a)[1]),"r"((a)[2]),"r"((a)[3]),"r"((b)[0]),"r"((b)[1]))

#define NSTG 3
#define TILE_B 16384
#define STAGE_BYTES 65536
static constexpr uint32_t GEMM_SMEM = NSTG*STAGE_BYTES;

// C = (Ahi+Alo)@(Bhi+Blo)^T + bias. MODE 0: C fp32. 1: relu+split. 2: split. 3: V-transpose split.
template<int MODE>
__global__ __launch_bounds__(256,1) void gemm_mma_kernel(
  const bf* __restrict__ Ahi, const bf* __restrict__ Alo,
  const bf* __restrict__ Bhi, const bf* __restrict__ Blo,
  const float* __restrict__ bias, float* __restrict__ C,
  bf* __restrict__ Chi, bf* __restrict__ Clo, int K, int M)
{
  extern __shared__ char smem[];
  const uint32_t sbase = smem_u32(smem);
  int tid=threadIdx.x, wid=tid>>5, lane=tid&31;
  int row0=blockIdx.y*128, col0=blockIdx.x*128;
  int rb=tid>>3, c8=(tid&7);
  const bf* base[4] = { Ahi+(size_t)row0*K, Alo+(size_t)row0*K,
                        Bhi+(size_t)col0*K, Blo+(size_t)col0*K };
  int KT = K>>6;

  auto load_chunk=[&](int kt,int s){
    uint32_t sb = sbase + (uint32_t)s*STAGE_BYTES;
    int k0e = kt<<6;
    #pragma unroll
    for(int i=0;i<16;i++){
      int t4=i>>2;
      int r=((i&3)<<5)+rb;
      uint32_t bo=(uint32_t)(r*128 + c8*16);
      cp16(sb+(uint32_t)(t4*TILE_B)+(bo^((bo>>3)&0x70)),
           base[t4]+(size_t)r*K+k0e+c8*8);
    }
  };

  float acc[4][4][4];
  #pragma unroll
  for(int mt=0;mt<4;mt++)
    #pragma unroll
    for(int nt=0;nt<4;nt++)
      #pragma unroll
      for(int j=0;j<4;j++) acc[mt][nt][j]=0.f;

  int wm = wid&1, wn = wid>>1;
  int mA = wm*64 + (lane&7) + ((lane>>3)&1)*8;
  int kAby = ((lane>>4)&1)*16;
  int nB = wn*32 + (lane&7) + ((lane>>4)&1)*8;
  int kBby = ((lane>>3)&1)*16;

  #pragma unroll
  for(int p=0;p<NSTG-1;p++){ load_chunk(p,p); CP_COMMIT(); }

  for(int kt=0;kt<KT;kt++){
    int pre = kt+NSTG-1;
    if(pre<KT) load_chunk(pre, pre%NSTG);
    CP_COMMIT();
    CP_WAIT(NSTG-2);
    __syncthreads();
    uint32_t sb = sbase + (uint32_t)(kt%NSTG)*STAGE_BYTES;
    uint32_t sAh=sb, sAl=sb+TILE_B, sBh=sb+2*TILE_B, sBl=sb+3*TILE_B;
    #pragma unroll
    for(int st=0; st<4; st++){
      int kby0 = st*32;
      uint32_t ah[16], al[16], bh4[8], bl4[8];
      #pragma unroll
      for(int mt=0;mt<4;mt++){
        int r = mA + mt*16;
        uint32_t off = (uint32_t)(r*128 + ((kby0+kAby) ^ ((r&7)*16)));
        LDSM4(&ah[mt*4], sAh+off);
        LDSM4(&al[mt*4], sAl+off);
      }
      #pragma unroll
      for(int bt=0;bt<2;bt++){
        int n = nB + bt*16;
        uint32_t off = (uint32_t)(n*128 + ((kby0+kBby) ^ ((n&7)*16)));
        LDSM4(&bh4[bt*4], sBh+off);
        LDSM4(&bl4[bt*4], sBl+off);
      }
      #pragma unroll
      for(int mt=0;mt<4;mt++){
        #pragma unroll
        for(int nt=0;nt<4;nt++){
          uint32_t* Bh2 = &bh4[(nt>>1)*4 + (nt&1)*2];
          uint32_t* Bl2 = &bl4[(nt>>1)*4 + (nt&1)*2];
          MMA_BF16(acc[mt][nt], &ah[mt*4], Bh2);
          MMA_BF16(acc[mt][nt], &ah[mt*4], Bl2);
          MMA_BF16(acc[mt][nt], &al[mt*4], Bh2);
        }
      }
    }
    __syncthreads();
  }

  #pragma unroll
  for(int mt=0;mt<4;mt++){
    int r0 = row0 + wm*64 + mt*16 + (lane>>2);
    #pragma unroll
    for(int nt=0;nt<4;nt++){
      int c0i = col0 + wn*32 + nt*8 + 2*(lane&3);
      float b0v=bias[c0i], b1v=bias[c0i+1];
      float* a = acc[mt][nt];
      float v00=a[0]+b0v, v01=a[1]+b1v, v10=a[2]+b0v, v11=a[3]+b1v;
      if(MODE==0){
        *(float2*)&C[(size_t)r0*M + c0i]     = make_float2(v00,v01);
        *(float2*)&C[(size_t)(r0+8)*M + c0i] = make_float2(v10,v11);
      } else if(MODE==1 || MODE==2){
        if(MODE==1){ v00=fmaxf(v00,0.f); v01=fmaxf(v01,0.f); v10=fmaxf(v10,0.f); v11=fmaxf(v11,0.f); }
        bf2 h0,l0,h1,l1;
        split_bf(v00,h0.x,l0.x); split_bf(v01,h0.y,l0.y);
        split_bf(v10,h1.x,l1.x); split_bf(v11,h1.y,l1.y);
        *(bf2*)&Chi[(size_t)r0*M + c0i]     = h0;
        *(bf2*)&Chi[(size_t)(r0+8)*M + c0i] = h1;
        *(bf2*)&Clo[(size_t)r0*M + c0i]     = l0;
        *(bf2*)&Clo[(size_t)(r0+8)*M + c0i] = l1;
      } else {
        // Vt[((b*H+h)*DH + d)*S + s]
        int bI=r0>>10, sI=r0&1023, hI=c0i>>6, dI=c0i&63;
        size_t db = ((size_t)bI*Hz + hI)*DHz;
        bf hh,ll;
        split_bf(v00,hh,ll); Chi[(db+dI)*Sz+sI]=hh;     Clo[(db+dI)*Sz+sI]=ll;
        split_bf(v01,hh,ll); Chi[(db+dI+1)*Sz+sI]=hh;   Clo[(db+dI+1)*Sz+sI]=ll;
        split_bf(v10,hh,ll); Chi[(db+dI)*Sz+sI+8]=hh;   Clo[(db+dI)*Sz+sI+8]=ll;
        split_bf(v11,hh,ll); Chi[(db+dI+1)*Sz+sI+8]=hh; Clo[(db+dI+1)*Sz+sI+8]=ll;
      }
    }
  }
}

// -------------------- fused flash attention --------------------
static constexpr uint32_t FLASH_SMEM = 32768 + 2*65536;   // Q + 2 KV stages

__global__ __launch_bounds__(256,1) void flash_kernel(
  const bf* __restrict__ Qhi, const bf* __restrict__ Qlo,
  const bf* __restrict__ Khi, const bf* __restrict__ Klo,
  const bf* __restrict__ Vthi, const bf* __restrict__ Vtlo,
  const int* __restrict__ lens,
  bf* __restrict__ Ohi, bf* __restrict__ Olo)
{
  extern __shared__ char smem[];
  uint32_t sb = smem_u32(smem);
  uint32_t sQh=sb, sQl=sb+16384;
  int tid=threadIdx.x, wid=tid>>5, lane=tid&31;
  int bh=blockIdx.y, b=bh>>3, h=bh&7;
  int q0=blockIdx.x*128;
  int len = lens[b];
  int ntiles = (len+127)>>7;

  size_t qrow = ((size_t)b*Sz+q0)*Dz + h*DHz;
  for(int u=tid; u<1024; u+=256){
    int r=u>>3, c=u&7;
    uint32_t off=(uint32_t)(r*128 + ((c*16) ^ ((r&7)*16)));
    cp16(sQh+off, Qhi+qrow+(size_t)r*Dz+c*8);
    cp16(sQl+off, Qlo+qrow+(size_t)r*Dz+c*8);
  }
  auto load_kv=[&](int kt,int stg){
    uint32_t s0 = sb + 32768 + (uint32_t)stg*65536;
    int k0 = kt<<7;
    size_t krow = ((size_t)b*Sz+k0)*Dz + h*DHz;
    for(int u=tid; u<1024; u+=256){
      int r=u>>3, c=u&7;
      uint32_t off=(uint32_t)(r*128 + ((c*16) ^ ((r&7)*16)));
      cp16(s0+off,       Khi+krow+(size_t)r*Dz+c*8);
      cp16(s0+16384+off, Klo+krow+(size_t)r*Dz+c*8);
    }
    size_t vrow = (size_t)bh*DHz*Sz + k0;
    for(int u=tid; u<1024; u+=256){
      int r=u>>4, c=u&15;
      uint32_t off=(uint32_t)(r*256 + ((c*16) ^ ((r&7)*16)));
      cp16(s0+32768+off, Vthi+vrow+(size_t)r*Sz+c*8);
      cp16(s0+49152+off, Vtlo+vrow+(size_t)r*Sz+c*8);
    }
  };
  load_kv(0,0);
  CP_COMMIT();

  float mrow0=-1e30f, mrow1=-1e30f, lrow0=0.f, lrow1=0.f;
  float oacc[8][4];
  #pragma unroll
  for(int i=0;i<8;i++){
    #pragma unroll
    for(int j=0;j<4;j++) oacc[i][j]=0.f; }

  int rA = wid*16 + (lane&7) + ((lane>>3)&1)*8;
  int kAby = ((lane>>4)&1)*16;
  int nBb = (lane&7) + ((lane>>4)&1)*8;
  int kBby = ((lane>>3)&1)*16;
  uint32_t offaQ[4];
  #pragma unroll
  for(int st=0;st<4;st++)
    offaQ[st]=(uint32_t)(rA*128 + ((st*32+kAby) ^ ((rA&7)*16)));

  for(int kt=0;kt<ntiles;kt++){
    if(kt+1<ntiles){ load_kv(kt+1,(kt+1)&1); CP_COMMIT(); CP_WAIT(1); }
    else CP_WAIT(0);
    __syncthreads();
    uint32_t s0 = sb + 32768 + (uint32_t)(kt&1)*65536;
    uint32_t sKh=s0, sKl=s0+16384, sVh=s0+32768, sVl=s0+49152;

    float sacc[16][4];
    #pragma unroll
    for(int i=0;i<16;i++){
      #pragma unroll
      for(int j=0;j<4;j++) sacc[i][j]=0.f; }

    #pragma unroll
    for(int st=0;st<4;st++){
      uint32_t ah[4], al[4];
      LDSM4(ah, sQh+offaQ[st]); LDSM4(al, sQl+offaQ[st]);
      #pragma unroll
      for(int g=0;g<8;g++){
        int n = g*16 + nBb;
        uint32_t offb=(uint32_t)(n*128 + ((st*32+kBby) ^ ((n&7)*16)));
        uint32_t bh4[4], bl4[4];
        LDSM4(bh4, sKh+offb); LDSM4(bl4, sKl+offb);
        MMA_BF16(sacc[2*g],  ah, &bh4[0]); MMA_BF16(sacc[2*g],  ah, &bl4[0]); MMA_BF16(sacc[2*g],  al, &bh4[0]);
        MMA_BF16(sacc[2*g+1],ah, &bh4[2]); MMA_BF16(sacc[2*g+1],ah, &bl4[2]); MMA_BF16(sacc[2*g+1],al, &bh4[2]);
      }
    }

    int k0 = kt<<7;
    bool need_mask = (k0+128 > len);
    #pragma unroll
    for(int nt=0;nt<16;nt++){
      #pragma unroll
      for(int j=0;j<4;j++){
        float s = sacc[nt][j]*0.125f;
        if(need_mask){
          int col = k0 + nt*8 + 2*(lane&3) + (j&1);
          if(col>=len) s=-1e30f;
        }
        sacc[nt][j]=s;
      }
    }
    float mx0=-1e30f, mx1=-1e30f;
    #pragma unroll
    for(int nt=0;nt<16;nt++){
      mx0=fmaxf(mx0,fmaxf(sacc[nt][0],sacc[nt][1]));
      mx1=fmaxf(mx1,fmaxf(sacc[nt][2],sacc[nt][3]));
    }
    mx0=fmaxf(mx0,__shfl_xor_sync(0xffffffffu,mx0,1));
    mx0=fmaxf(mx0,__shfl_xor_sync(0xffffffffu,mx0,2));
    mx1=fmaxf(mx1,__shfl_xor_sync(0xffffffffu,mx1,1));
    mx1=fmaxf(mx1,__shfl_xor_sync(0xffffffffu,mx1,2));
    float mn0=fmaxf(mrow0,mx0), mn1=fmaxf(mrow1,mx1);
    float sc0=__expf(mrow0-mn0), sc1=__expf(mrow1-mn1);
    mrow0=mn0; mrow1=mn1;
    float sum0=0.f, sum1=0.f;
    #pragma unroll
    for(int nt=0;nt<16;nt++){
      float p0=__expf(sacc[nt][0]-mn0), p1=__expf(sacc[nt][1]-mn0);
      float p2=__expf(sacc[nt][2]-mn1), p3=__expf(sacc[nt][3]-mn1);
      sacc[nt][0]=p0; sacc[nt][1]=p1; sacc[nt][2]=p2; sacc[nt][3]=p3;
      sum0+=p0+p1; sum1+=p2+p3;
    }
    sum0+=__shfl_xor_sync(0xffffffffu,sum0,1);
    sum0+=__shfl_xor_sync(0xffffffffu,sum0,2);
    sum1+=__shfl_xor_sync(0xffffffffu,sum1,1);
    sum1+=__shfl_xor_sync(0xffffffffu,sum1,2);
    lrow0=lrow0*sc0+sum0; lrow1=lrow1*sc1+sum1;
    #pragma unroll
    for(int nt=0;nt<8;nt++){
      oacc[nt][0]*=sc0; oacc[nt][1]*=sc0; oacc[nt][2]*=sc1; oacc[nt][3]*=sc1;
    }

    #pragma unroll
    for(int j=0;j<8;j++){
      uint32_t pah[4], pal[4];
      {
        bf h0,l0,h1,l1;
        split_bf(sacc[2*j][0],h0,l0);   split_bf(sacc[2*j][1],h1,l1);
        pah[0]=pack2(h0,h1); pal[0]=pack2(l0,l1);
        split_bf(sacc[2*j][2],h0,l0);   split_bf(sacc[2*j][3],h1,l1);
        pah[1]=pack2(h0,h1); pal[1]=pack2(l0,l1);
        split_bf(sacc[2*j+1][0],h0,l0); split_bf(sacc[2*j+1][1],h1,l1);
        pah[2]=pack2(h0,h1); pal[2]=pack2(l0,l1);
        split_bf(sacc[2*j+1][2],h0,l0); split_bf(sacc[2*j+1][3],h1,l1);
        pah[3]=pack2(h0,h1); pal[3]=pack2(l0,l1);
      }
      #pragma unroll
      for(int g=0;g<4;g++){
        int n = g*16 + nBb;
        uint32_t offv=(uint32_t)(n*256 + ((j*32+kBby) ^ ((n&7)*16)));
        uint32_t vh4[4], vl4[4];
        LDSM4(vh4, sVh+offv); LDSM4(vl4, sVl+offv);
        MMA_BF16(oacc[2*g],  pah, &vh4[0]); MMA_BF16(oacc[2*g],  pah, &vl4[0]); MMA_BF16(oacc[2*g],  pal, &vh4[0]);
        MMA_BF16(oacc[2*g+1],pah, &vh4[2]); MMA_BF16(oacc[2*g+1],pah, &vl4[2]); MMA_BF16(oacc[2*g+1],pal, &vh4[2]);
      }
    }
    __syncthreads();
  }

  float li0=1.f/lrow0, li1=1.f/lrow1;
  int r0 = q0 + wid*16 + (lane>>2);
  #pragma unroll
  for(int nt=0;nt<8;nt++){
    int c = h*64 + nt*8 + 2*(lane&3);
    size_t o0 = ((size_t)b*Sz+r0)*Dz + c;
    size_t o1 = o0 + (size_t)8*Dz;
    bf2 hh,ll;
    split_bf(oacc[nt][0]*li0, hh.x, ll.x);
    split_bf(oacc[nt][1]*li0, hh.y, ll.y);
    *(bf2*)&Ohi[o0]=hh; *(bf2*)&Olo[o0]=ll;
    split_bf(oacc[nt][2]*li1, hh.x, ll.x);
    split_bf(oacc[nt][3]*li1, hh.y, ll.y);
    *(bf2*)&Ohi[o1]=hh; *(bf2*)&Olo[o1]=ll;
  }
}

// -------------------- small kernels --------------------
__global__ __launch_bounds__(256) void wsplit_kernel(
  const float* __restrict__ W, bf* __restrict__ thi, bf* __restrict__ tlo,
  int K, int M)
{
  __shared__ float t[32][33];
  int tx=threadIdx.x, ty=threadIdx.y;
  int m0=blockIdx.x*32, k0=blockIdx.y*32;
  size_t zo = (size_t)blockIdx.z*K*M;
  const float* Wz = W + zo;
  #pragma unroll
  for(int j=0;j<4;j++) t[ty+8*j][tx] = Wz[(size_t)(k0+ty+8*j)*M + m0+tx];
  __syncthreads();
  #pragma unroll
  for(int j=0;j<4;j++){
    float v = t[tx][ty+8*j];
    bf h,l; split_bf(v,h,l);
    size_t o = zo + (size_t)(m0+ty+8*j)*K + k0+tx;
    thi[o]=h; tlo[o]=l;
  }
}

__global__ __launch_bounds__(256) void posenc_kernel(const float* __restrict__ x,
  float* __restrict__ out, bf* __restrict__ ohi, bf* __restrict__ olo)
{
  int idx = blockIdx.x*256 + threadIdx.x;
  int d = idx & (Dz-1), s = (idx>>9) & (Sz-1);
  int i2 = d & ~1;
  float divv = (float)exp((double)i2 * (-9.210340371976184/(double)Dz));
  float ang = (float)s * divv;
  float pe = (d&1) ? cosf(ang) : sinf(ang);
  float v = x[idx] + pe;
  out[idx] = v;
  bf h,l; split_bf(v,h,l);
  ohi[idx]=h; olo[idx]=l;
}

template<bool SPLIT>
__global__ __launch_bounds__(256) void ln_kernel(
  const float* __restrict__ Xa, const float* __restrict__ Xb,
  const float* __restrict__ g, const float* __restrict__ be,
  float* __restrict__ out, bf* __restrict__ ohi, bf* __restrict__ olo)
{
  int n=blockIdx.x;
  const float* a = Xa + (size_t)n*Dz;
  const float* c = Xb + (size_t)n*Dz;
  int tid=threadIdx.x, lane=tid&31, w=tid>>5;
  __shared__ float sh[8];
  float s0=a[tid]+c[tid], s1=a[tid+256]+c[tid+256];
  float sum=s0+s1;
  #pragma unroll
  for(int o=16;o;o>>=1) sum+=__shfl_xor_sync(0xffffffffu,sum,o);
  if(lane==0) sh[w]=sum;
  __syncthreads();
  float tot=0.f;
  #pragma unroll
  for(int i=0;i<8;i++) tot+=sh[i];
  __syncthreads();
  float mean=tot*(1.0f/(float)Dz);
  float d0=s0-mean, d1=s1-mean;
  float ss=d0*d0+d1*d1;
  #pragma unroll
  for(int o=16;o;o>>=1) ss+=__shfl_xor_sync(0xffffffffu,ss,o);
  if(lane==0) sh[w]=ss;
  __syncthreads();
  float tot2=0.f;
  #pragma unroll
  for(int i=0;i<8;i++) tot2+=sh[i];
  float var=tot2*(1.0f/(float)(Dz-1));
  float r=1.0f/(sqrtf(var)+1e-6f);
  float v0=g[tid]*d0*r+be[tid];
  float v1=g[tid+256]*d1*r+be[tid+256];
  size_t o0=(size_t)n*Dz+tid, o1=o0+256;
  out[o0]=v0; out[o1]=v1;
  if (SPLIT){
    bf h,l;
    split_bf(v0,h,l); ohi[o0]=h; olo[o0]=l;
    split_bf(v1,h,l); ohi[o1]=h; olo[o1]=l;
  }
}

extern "C" void kernel_launch(void* const* d_in, const int* in_sizes, int n_in,
                              void* d_out, int out_size)
{
  const float* x  =(const float*)d_in[0];
  const int* lens =(const int*)d_in[1];
  const float* Wq =(const float*)d_in[2];  const float* bq =(const float*)d_in[3];
  const float* Wk =(const float*)d_in[4];  const float* bk =(const float*)d_in[5];
  const float* Wv =(const float*)d_in[6];  const float* bv =(const float*)d_in[7];
  const float* Wo =(const float*)d_in[8];  const float* bo =(const float*)d_in[9];
  const float* W1 =(const float*)d_in[10]; const float* b1 =(const float*)d_in[11];
  const float* W2 =(const float*)d_in[12]; const float* b2 =(const float*)d_in[13];
  const float* g1 =(const float*)d_in[14]; const float* be1=(const float*)d_in[15];
  const float* g2 =(const float*)d_in[16]; const float* be2=(const float*)d_in[17];

  float* sc=nullptr;
  cudaGetSymbolAddress((void**)&sc, g_scratch);
  float *xb=sc+XBUF, *tb=sc+TBUF, *yb=sc+YBUF;
  bf *qhi=(bf*)(sc+QHIo), *qlo=(bf*)(sc+QLOo);
  bf *khi=(bf*)(sc+KHIo), *klo=(bf*)(sc+KLOo);
  bf *vthi=(bf*)(sc+VTHIo), *vtlo=(bf*)(sc+VTLOo);
  bf *abhi=(bf*)(sc+ABHIo), *ablo=(bf*)(sc+ABLOo);
  bf *xhi=(bf*)(sc+XHIo), *xlo=(bf*)(sc+XLOo);
  bf *yhi=(bf*)(sc+YHIo), *ylo=(bf*)(sc+YLOo);
  bf *fhi=(bf*)(sc+FHIo), *flo=(bf*)(sc+FLOo);
  bf *wqh=(bf*)(sc+WQo), *wql=wqh+WPROJ;
  bf *wkh=(bf*)(sc+WKo), *wkl=wkh+WPROJ;
  bf *wvh=(bf*)(sc+WVo), *wvl=wvh+WPROJ;
  bf *woh=(bf*)(sc+WOo), *wol=woh+WPROJ;
  bf *w1h=(bf*)(sc+W1o), *w1l=w1h+WFF;
  bf *w2h=(bf*)(sc+W2o), *w2l=w2h+WFF;

  cudaFuncSetAttribute(gemm_mma_kernel<0>, cudaFuncAttributeMaxDynamicSharedMemorySize, GEMM_SMEM);
  cudaFuncSetAttribute(gemm_mma_kernel<1>, cudaFuncAttributeMaxDynamicSharedMemorySize, GEMM_SMEM);
  cudaFuncSetAttribute(gemm_mma_kernel<2>, cudaFuncAttributeMaxDynamicSharedMemorySize, GEMM_SMEM);
  cudaFuncSetAttribute(gemm_mma_kernel<3>, cudaFuncAttributeMaxDynamicSharedMemorySize, GEMM_SMEM);
  cudaFuncSetAttribute(flash_kernel, cudaFuncAttributeMaxDynamicSharedMemorySize, FLASH_SMEM);

  dim3 wb(32,8);
  wsplit_kernel<<<dim3(Dz/32,Dz/32,Lz), wb>>>(Wq, wqh, wql, Dz, Dz);
  wsplit_kernel<<<dim3(Dz/32,Dz/32,Lz), wb>>>(Wk, wkh, wkl, Dz, Dz);
  wsplit_kernel<<<dim3(Dz/32,Dz/32,Lz), wb>>>(Wv, wvh, wvl, Dz, Dz);
  wsplit_kernel<<<dim3(Dz/32,Dz/32,Lz), wb>>>(Wo, woh, wol, Dz, Dz);
  wsplit_kernel<<<dim3(FFz/32,Dz/32,Lz), wb>>>(W1, w1h, w1l, Dz, FFz);
  wsplit_kernel<<<dim3(Dz/32,FFz/32,Lz), wb>>>(W2, w2h, w2l, FFz, Dz);

  posenc_kernel<<<(Nz*Dz)/256, 256>>>(x, xb, xhi, xlo);

  dim3 gproj(Dz/128, Nz/128);
  dim3 gff1(FFz/128, Nz/128);

  for (int l=0;l<Lz;l++){
    size_t wp=(size_t)l*Dz*Dz, wf=(size_t)l*Dz*FFz;
    gemm_mma_kernel<2><<<gproj,256,GEMM_SMEM>>>(xhi,xlo, wqh+wp,wql+wp, bq+l*Dz, nullptr,qhi,qlo, Dz,Dz);
    gemm_mma_kernel<2><<<gproj,256,GEMM_SMEM>>>(xhi,xlo, wkh+wp,wkl+wp, bk+l*Dz, nullptr,khi,klo, Dz,Dz);
    gemm_mma_kernel<3><<<gproj,256,GEMM_SMEM>>>(xhi,xlo, wvh+wp,wvl+wp, bv+l*Dz, nullptr,vthi,vtlo, Dz,Dz);

    flash_kernel<<<dim3(Sz/128, Bz*Hz),256,FLASH_SMEM>>>(qhi,qlo,khi,klo,vthi,vtlo,lens,abhi,ablo);

    gemm_mma_kernel<0><<<gproj,256,GEMM_SMEM>>>(abhi,ablo, woh+wp,wol+wp, bo+l*Dz, tb,nullptr,nullptr, Dz,Dz);
    ln_kernel<true><<<Nz,256>>>(xb,tb,g1+l*Dz,be1+l*Dz, yb,yhi,ylo);

    gemm_mma_kernel<1><<<gff1,256,GEMM_SMEM>>>(yhi,ylo, w1h+wf,w1l+wf, b1+(size_t)l*FFz, nullptr,fhi,flo, Dz,FFz);
    gemm_mma_kernel<0><<<gproj,256,GEMM_SMEM>>>(fhi,flo, w2h+wf,w2l+wf, b2+l*Dz, tb,nullptr,nullptr, FFz,Dz);

    if (l==Lz-1)
      ln_kernel<false><<<Nz,256>>>(yb,tb,g2+l*Dz,be2+l*Dz,(float*)d_out,nullptr,nullptr);
    else
      ln_kernel<true><<<Nz,256>>>(yb,tb,g2+l*Dz,be2+l*Dz, xb,xhi,xlo);
  }
}

// round 7
// speedup vs baseline: 3.1726x; 1.0180x over previous
#include <cuda_runtime.h>
#include <cuda_bf16.h>
#include <cstdint>
#include <math.h>

#define Bz 8
#define Sz 1024
#define Dz 512
#define Hz 8
#define DHz 64
#define FFz 2048
#define Lz 4
#define Nz (Bz*Sz)

typedef __nv_bfloat16 bf;
typedef __nv_bfloat162 bf2;

static constexpr size_t NB = (size_t)Nz*Dz;
static constexpr size_t FBsz = (size_t)Nz*FFz;
static constexpr size_t WPROJ = (size_t)Lz*Dz*Dz;
static constexpr size_t WFF = (size_t)Lz*Dz*FFz;

static constexpr size_t XBUF=0, TBUF=NB, YBUF=2*NB,
  QHIo=3*NB, QLOo=QHIo+NB/2, KHIo=QLOo+NB/2, KLOo=KHIo+NB/2,
  VTHIo=KLOo+NB/2, VTLOo=VTHIo+NB/2, ABHIo=VTLOo+NB/2, ABLOo=ABHIo+NB/2,
  XHIo=ABLOo+NB/2, XLOo=XHIo+NB/2, YHIo=XLOo+NB/2, YLOo=YHIo+NB/2,
  FHIo=YLOo+NB/2, FLOo=FHIo+FBsz/2,
  WQo=FLOo+FBsz/2, WKo=WQo+WPROJ, WVo=WKo+WPROJ, WOo=WVo+WPROJ,
  W1o=WOo+WPROJ, W2o=W1o+WFF, SCRATCH_TOTAL=W2o+WFF;

__device__ float g_scratch[SCRATCH_TOTAL];

__device__ __forceinline__ uint32_t smem_u32(const void* p){ return (uint32_t)__cvta_generic_to_shared(p); }
__device__ __forceinline__ void split_bf(float v, bf& h, bf& l){
  h = __float2bfloat16(v);
  l = __float2bfloat16(v - __bfloat162float(h));
}
__device__ __forceinline__ uint32_t pack2(bf a, bf b){
  bf2 t; t.x=a; t.y=b; uint32_t r; memcpy(&r,&t,4); return r; }

__device__ __forceinline__ void cp16(uint32_t d,const void* s){
  asm volatile("cp.async.cg.shared.global [%0],[%1],16;"::"r"(d),"l"(s):"memory"); }
#define CP_COMMIT() asm volatile("cp.async.commit_group;":::"memory")
#define CP_WAIT(n) asm volatile("cp.async.wait_group %0;"::"n"(n):"memory")

#define LDSM4(r,addr) asm volatile("ldmatrix.sync.aligned.m8n8.x4.shared.b16 {%0,%1,%2,%3},[%4];" \
  :"=r"((r)[0]),"=r"((r)[1]),"=r"((r)[2]),"=r"((r)[3]):"r"(addr))

#define MMA_BF16(c,a,b) asm volatile( \
  "mma.sync.aligned.m16n8k16.row.col.f32.bf16.bf16.f32 {%0,%1,%2,%3},{%4,%5,%6,%7},{%8,%9},{%0,%1,%2,%3};" \
  : "+f"((c)[0]),"+f"((c)[1]),"+f"((c)[2]),"+f"((c)[3]) \
  : "r"((a)[0]),"r"((a)[1]),"r"((a)[2]),"r"((a)[3]),"r"((b)[0]),"r"((b)[1]))

// GEMM: K-chunk 32, 64B rows, swizzle chunk16 ^= (r>>1)&3
#define NSTG 3
#define TILE_B2 8192            // 128 rows x 64 B
#define STAGE_B2 32768          // 4 tiles
static constexpr uint32_t GEMM_SMEM = NSTG*STAGE_B2;   // 96 KB -> 2 CTA/SM

__device__ __forceinline__ uint32_t swz64(int r, int kby){
  return (uint32_t)(r*64 + ((((kby>>4) ^ ((r>>1)&3)))<<4));
}

// C = (Ahi+Alo)@(Bhi+Blo)^T + bias. MODE 0: C fp32. 1: relu+split. 2: split. 3: V-transpose split.
template<int MODE>
__global__ __launch_bounds__(256,2) void gemm_mma_kernel(
  const bf* __restrict__ Ahi, const bf* __restrict__ Alo,
  const bf* __restrict__ Bhi, const bf* __restrict__ Blo,
  const float* __restrict__ bias, float* __restrict__ C,
  bf* __restrict__ Chi, bf* __restrict__ Clo, int K, int M)
{
  extern __shared__ char smem[];
  const uint32_t sbase = smem_u32(smem);
  int tid=threadIdx.x, wid=tid>>5, lane=tid&31;
  int row0=blockIdx.y*128, col0=blockIdx.x*128;
  const bf* base[4] = { Ahi+(size_t)row0*K, Alo+(size_t)row0*K,
                        Bhi+(size_t)col0*K, Blo+(size_t)col0*K };
  int KT = K>>5;                 // chunks of 32

  auto load_chunk=[&](int kt,int s){
    uint32_t sb = sbase + (uint32_t)s*STAGE_B2;
    int k0e = kt<<5;
    #pragma unroll
    for(int i=0;i<8;i++){
      int t4=i>>1;
      int u = ((i&1)<<8) + tid;       // 0..511
      int r = u>>2, c = u&3;          // c: 16B chunk
      cp16(sb + (uint32_t)(t4*TILE_B2) + swz64(r, c<<4),
           base[t4] + (size_t)r*K + k0e + c*8);
    }
  };

  float acc[4][4][4];
  #pragma unroll
  for(int mt=0;mt<4;mt++)
    #pragma unroll
    for(int nt=0;nt<4;nt++)
      #pragma unroll
      for(int j=0;j<4;j++) acc[mt][nt][j]=0.f;

  int wm = wid&1, wn = wid>>1;
  int mA = wm*64 + (lane&7) + ((lane>>3)&1)*8;
  int kAby = ((lane>>4)&1)*16;
  int nB = wn*32 + (lane&7) + ((lane>>4)&1)*8;
  int kBby = ((lane>>3)&1)*16;

  #pragma unroll
  for(int p=0;p<NSTG-1;p++){ load_chunk(p,p); CP_COMMIT(); }

  for(int kt=0;kt<KT;kt++){
    int pre = kt+NSTG-1;
    if(pre<KT) load_chunk(pre, pre%NSTG);
    CP_COMMIT();
    CP_WAIT(NSTG-2);
    __syncthreads();
    uint32_t sb = sbase + (uint32_t)(kt%NSTG)*STAGE_B2;
    uint32_t sAh=sb, sAl=sb+TILE_B2, sBh=sb+2*TILE_B2, sBl=sb+3*TILE_B2;
    #pragma unroll
    for(int st=0; st<2; st++){
      int kby0 = st*32;
      uint32_t ah[16], al[16], bh4[8], bl4[8];
      #pragma unroll
      for(int mt=0;mt<4;mt++){
        int r = mA + mt*16;
        uint32_t off = swz64(r, kby0+kAby);
        LDSM4(&ah[mt*4], sAh+off);
        LDSM4(&al[mt*4], sAl+off);
      }
      #pragma unroll
      for(int bt=0;bt<2;bt++){
        int n = nB + bt*16;
        uint32_t off = swz64(n, kby0+kBby);
        LDSM4(&bh4[bt*4], sBh+off);
        LDSM4(&bl4[bt*4], sBl+off);
      }
      #pragma unroll
      for(int mt=0;mt<4;mt++){
        #pragma unroll
        for(int nt=0;nt<4;nt++){
          uint32_t* Bh2 = &bh4[(nt>>1)*4 + (nt&1)*2];
          uint32_t* Bl2 = &bl4[(nt>>1)*4 + (nt&1)*2];
          MMA_BF16(acc[mt][nt], &ah[mt*4], Bh2);
          MMA_BF16(acc[mt][nt], &ah[mt*4], Bl2);
          MMA_BF16(acc[mt][nt], &al[mt*4], Bh2);
        }
      }
    }
    __syncthreads();
  }

  #pragma unroll
  for(int mt=0;mt<4;mt++){
    int r0 = row0 + wm*64 + mt*16 + (lane>>2);
    #pragma unroll
    for(int nt=0;nt<4;nt++){
      int c0i = col0 + wn*32 + nt*8 + 2*(lane&3);
      float b0v=bias[c0i], b1v=bias[c0i+1];
      float* a = acc[mt][nt];
      float v00=a[0]+b0v, v01=a[1]+b1v, v10=a[2]+b0v, v11=a[3]+b1v;
      if(MODE==0){
        *(float2*)&C[(size_t)r0*M + c0i]     = make_float2(v00,v01);
        *(float2*)&C[(size_t)(r0+8)*M + c0i] = make_float2(v10,v11);
      } else if(MODE==1 || MODE==2){
        if(MODE==1){ v00=fmaxf(v00,0.f); v01=fmaxf(v01,0.f); v10=fmaxf(v10,0.f); v11=fmaxf(v11,0.f); }
        bf2 h0,l0,h1,l1;
        split_bf(v00,h0.x,l0.x); split_bf(v01,h0.y,l0.y);
        split_bf(v10,h1.x,l1.x); split_bf(v11,h1.y,l1.y);
        *(bf2*)&Chi[(size_t)r0*M + c0i]     = h0;
        *(bf2*)&Chi[(size_t)(r0+8)*M + c0i] = h1;
        *(bf2*)&Clo[(size_t)r0*M + c0i]     = l0;
        *(bf2*)&Clo[(size_t)(r0+8)*M + c0i] = l1;
      } else {
        int bI=r0>>10, sI=r0&1023, hI=c0i>>6, dI=c0i&63;
        size_t db = ((size_t)bI*Hz + hI)*DHz;
        bf hh,ll;
        split_bf(v00,hh,ll); Chi[(db+dI)*Sz+sI]=hh;     Clo[(db+dI)*Sz+sI]=ll;
        split_bf(v01,hh,ll); Chi[(db+dI+1)*Sz+sI]=hh;   Clo[(db+dI+1)*Sz+sI]=ll;
        split_bf(v10,hh,ll); Chi[(db+dI)*Sz+sI+8]=hh;   Clo[(db+dI)*Sz+sI+8]=ll;
        split_bf(v11,hh,ll); Chi[(db+dI+1)*Sz+sI+8]=hh; Clo[(db+dI+1)*Sz+sI+8]=ll;
      }
    }
  }
}

// -------------------- fused flash attention (unchanged) --------------------
static constexpr uint32_t FLASH_SMEM = 32768 + 2*65536;

__global__ __launch_bounds__(256,1) void flash_kernel(
  const bf* __restrict__ Qhi, const bf* __restrict__ Qlo,
  const bf* __restrict__ Khi, const bf* __restrict__ Klo,
  const bf* __restrict__ Vthi, const bf* __restrict__ Vtlo,
  const int* __restrict__ lens,
  bf* __restrict__ Ohi, bf* __restrict__ Olo)
{
  extern __shared__ char smem[];
  uint32_t sb = smem_u32(smem);
  uint32_t sQh=sb, sQl=sb+16384;
  int tid=threadIdx.x, wid=tid>>5, lane=tid&31;
  int bh=blockIdx.y, b=bh>>3, h=bh&7;
  int q0=blockIdx.x*128;
  int len = lens[b];
  int ntiles = (len+127)>>7;

  size_t qrow = ((size_t)b*Sz+q0)*Dz + h*DHz;
  for(int u=tid; u<1024; u+=256){
    int r=u>>3, c=u&7;
    uint32_t off=(uint32_t)(r*128 + ((c*16) ^ ((r&7)*16)));
    cp16(sQh+off, Qhi+qrow+(size_t)r*Dz+c*8);
    cp16(sQl+off, Qlo+qrow+(size_t)r*Dz+c*8);
  }
  auto load_kv=[&](int kt,int stg){
    uint32_t s0 = sb + 32768 + (uint32_t)stg*65536;
    int k0 = kt<<7;
    size_t krow = ((size_t)b*Sz+k0)*Dz + h*DHz;
    for(int u=tid; u<1024; u+=256){
      int r=u>>3, c=u&7;
      uint32_t off=(uint32_t)(r*128 + ((c*16) ^ ((r&7)*16)));
      cp16(s0+off,       Khi+krow+(size_t)r*Dz+c*8);
      cp16(s0+16384+off, Klo+krow+(size_t)r*Dz+c*8);
    }
    size_t vrow = (size_t)bh*DHz*Sz + k0;
    for(int u=tid; u<1024; u+=256){
      int r=u>>4, c=u&15;
      uint32_t off=(uint32_t)(r*256 + ((c*16) ^ ((r&7)*16)));
      cp16(s0+32768+off, Vthi+vrow+(size_t)r*Sz+c*8);
      cp16(s0+49152+off, Vtlo+vrow+(size_t)r*Sz+c*8);
    }
  };
  load_kv(0,0);
  CP_COMMIT();

  float mrow0=-1e30f, mrow1=-1e30f, lrow0=0.f, lrow1=0.f;
  float oacc[8][4];
  #pragma unroll
  for(int i=0;i<8;i++){
    #pragma unroll
    for(int j=0;j<4;j++) oacc[i][j]=0.f; }

  int rA = wid*16 + (lane&7) + ((lane>>3)&1)*8;
  int kAby = ((lane>>4)&1)*16;
  int nBb = (lane&7) + ((lane>>4)&1)*8;
  int kBby = ((lane>>3)&1)*16;
  uint32_t offaQ[4];
  #pragma unroll
  for(int st=0;st<4;st++)
    offaQ[st]=(uint32_t)(rA*128 + ((st*32+kAby) ^ ((rA&7)*16)));

  for(int kt=0;kt<ntiles;kt++){
    if(kt+1<ntiles){ load_kv(kt+1,(kt+1)&1); CP_COMMIT(); CP_WAIT(1); }
    else CP_WAIT(0);
    __syncthreads();
    uint32_t s0 = sb + 32768 + (uint32_t)(kt&1)*65536;
    uint32_t sKh=s0, sKl=s0+16384, sVh=s0+32768, sVl=s0+49152;

    float sacc[16][4];
    #pragma unroll
    for(int i=0;i<16;i++){
      #pragma unroll
      for(int j=0;j<4;j++) sacc[i][j]=0.f; }

    #pragma unroll
    for(int st=0;st<4;st++){
      uint32_t ah[4], al[4];
      LDSM4(ah, sQh+offaQ[st]); LDSM4(al, sQl+offaQ[st]);
      #pragma unroll
      for(int g=0;g<8;g++){
        int n = g*16 + nBb;
        uint32_t offb=(uint32_t)(n*128 + ((st*32+kBby) ^ ((n&7)*16)));
        uint32_t bh4[4], bl4[4];
        LDSM4(bh4, sKh+offb); LDSM4(bl4, sKl+offb);
        MMA_BF16(sacc[2*g],  ah, &bh4[0]); MMA_BF16(sacc[2*g],  ah, &bl4[0]); MMA_BF16(sacc[2*g],  al, &bh4[0]);
        MMA_BF16(sacc[2*g+1],ah, &bh4[2]); MMA_BF16(sacc[2*g+1],ah, &bl4[2]); MMA_BF16(sacc[2*g+1],al, &bh4[2]);
      }
    }

    int k0 = kt<<7;
    bool need_mask = (k0+128 > len);
    #pragma unroll
    for(int nt=0;nt<16;nt++){
      #pragma unroll
      for(int j=0;j<4;j++){
        float s = sacc[nt][j]*0.125f;
        if(need_mask){
          int col = k0 + nt*8 + 2*(lane&3) + (j&1);
          if(col>=len) s=-1e30f;
        }
        sacc[nt][j]=s;
      }
    }
    float mx0=-1e30f, mx1=-1e30f;
    #pragma unroll
    for(int nt=0;nt<16;nt++){
      mx0=fmaxf(mx0,fmaxf(sacc[nt][0],sacc[nt][1]));
      mx1=fmaxf(mx1,fmaxf(sacc[nt][2],sacc[nt][3]));
    }
    mx0=fmaxf(mx0,__shfl_xor_sync(0xffffffffu,mx0,1));
    mx0=fmaxf(mx0,__shfl_xor_sync(0xffffffffu,mx0,2));
    mx1=fmaxf(mx1,__shfl_xor_sync(0xffffffffu,mx1,1));
    mx1=fmaxf(mx1,__shfl_xor_sync(0xffffffffu,mx1,2));
    float mn0=fmaxf(mrow0,mx0), mn1=fmaxf(mrow1,mx1);
    float sc0=__expf(mrow0-mn0), sc1=__expf(mrow1-mn1);
    mrow0=mn0; mrow1=mn1;
    float sum0=0.f, sum1=0.f;
    #pragma unroll
    for(int nt=0;nt<16;nt++){
      float p0=__expf(sacc[nt][0]-mn0), p1=__expf(sacc[nt][1]-mn0);
      float p2=__expf(sacc[nt][2]-mn1), p3=__expf(sacc[nt][3]-mn1);
      sacc[nt][0]=p0; sacc[nt][1]=p1; sacc[nt][2]=p2; sacc[nt][3]=p3;
      sum0+=p0+p1; sum1+=p2+p3;
    }
    sum0+=__shfl_xor_sync(0xffffffffu,sum0,1);
    sum0+=__shfl_xor_sync(0xffffffffu,sum0,2);
    sum1+=__shfl_xor_sync(0xffffffffu,sum1,1);
    sum1+=__shfl_xor_sync(0xffffffffu,sum1,2);
    lrow0=lrow0*sc0+sum0; lrow1=lrow1*sc1+sum1;
    #pragma unroll
    for(int nt=0;nt<8;nt++){
      oacc[nt][0]*=sc0; oacc[nt][1]*=sc0; oacc[nt][2]*=sc1; oacc[nt][3]*=sc1;
    }

    #pragma unroll
    for(int j=0;j<8;j++){
      uint32_t pah[4], pal[4];
      {
        bf h0,l0,h1,l1;
        split_bf(sacc[2*j][0],h0,l0);   split_bf(sacc[2*j][1],h1,l1);
        pah[0]=pack2(h0,h1); pal[0]=pack2(l0,l1);
        split_bf(sacc[2*j][2],h0,l0);   split_bf(sacc[2*j][3],h1,l1);
        pah[1]=pack2(h0,h1); pal[1]=pack2(l0,l1);
        split_bf(sacc[2*j+1][0],h0,l0); split_bf(sacc[2*j+1][1],h1,l1);
        pah[2]=pack2(h0,h1); pal[2]=pack2(l0,l1);
        split_bf(sacc[2*j+1][2],h0,l0); split_bf(sacc[2*j+1][3],h1,l1);
        pah[3]=pack2(h0,h1); pal[3]=pack2(l0,l1);
      }
      #pragma unroll
      for(int g=0;g<4;g++){
        int n = g*16 + nBb;
        uint32_t offv=(uint32_t)(n*256 + ((j*32+kBby) ^ ((n&7)*16)));
        uint32_t vh4[4], vl4[4];
        LDSM4(vh4, sVh+offv); LDSM4(vl4, sVl+offv);
        MMA_BF16(oacc[2*g],  pah, &vh4[0]); MMA_BF16(oacc[2*g],  pah, &vl4[0]); MMA_BF16(oacc[2*g],  pal, &vh4[0]);
        MMA_BF16(oacc[2*g+1],pah, &vh4[2]); MMA_BF16(oacc[2*g+1],pah, &vl4[2]); MMA_BF16(oacc[2*g+1],pal, &vh4[2]);
      }
    }
    __syncthreads();
  }

  float li0=1.f/lrow0, li1=1.f/lrow1;
  int r0 = q0 + wid*16 + (lane>>2);
  #pragma unroll
  for(int nt=0;nt<8;nt++){
    int c = h*64 + nt*8 + 2*(lane&3);
    size_t o0 = ((size_t)b*Sz+r0)*Dz + c;
    size_t o1 = o0 + (size_t)8*Dz;
    bf2 hh,ll;
    split_bf(oacc[nt][0]*li0, hh.x, ll.x);
    split_bf(oacc[nt][1]*li0, hh.y, ll.y);
    *(bf2*)&Ohi[o0]=hh; *(bf2*)&Olo[o0]=ll;
    split_bf(oacc[nt][2]*li1, hh.x, ll.x);
    split_bf(oacc[nt][3]*li1, hh.y, ll.y);
    *(bf2*)&Ohi[o1]=hh; *(bf2*)&Olo[o1]=ll;
  }
}

// -------------------- small kernels --------------------
__global__ __launch_bounds__(256) void wsplit_kernel(
  const float* __restrict__ W, bf* __restrict__ thi, bf* __restrict__ tlo,
  int K, int M)
{
  __shared__ float t[32][33];
  int tx=threadIdx.x, ty=threadIdx.y;
  int m0=blockIdx.x*32, k0=blockIdx.y*32;
  size_t zo = (size_t)blockIdx.z*K*M;
  const float* Wz = W + zo;
  #pragma unroll
  for(int j=0;j<4;j++) t[ty+8*j][tx] = Wz[(size_t)(k0+ty+8*j)*M + m0+tx];
  __syncthreads();
  #pragma unroll
  for(int j=0;j<4;j++){
    float v = t[tx][ty+8*j];
    bf h,l; split_bf(v,h,l);
    size_t o = zo + (size_t)(m0+ty+8*j)*K + k0+tx;
    thi[o]=h; tlo[o]=l;
  }
}

__global__ __launch_bounds__(256) void posenc_kernel(const float* __restrict__ x,
  float* __restrict__ out, bf* __restrict__ ohi, bf* __restrict__ olo)
{
  int idx = blockIdx.x*256 + threadIdx.x;
  int d = idx & (Dz-1), s = (idx>>9) & (Sz-1);
  int i2 = d & ~1;
  float divv = (float)exp((double)i2 * (-9.210340371976184/(double)Dz));
  float ang = (float)s * divv;
  float pe = (d&1) ? cosf(ang) : sinf(ang);
  float v = x[idx] + pe;
  out[idx] = v;
  bf h,l; split_bf(v,h,l);
  ohi[idx]=h; olo[idx]=l;
}

template<bool SPLIT>
__global__ __launch_bounds__(256) void ln_kernel(
  const float* __restrict__ Xa, const float* __restrict__ Xb,
  const float* __restrict__ g, const float* __restrict__ be,
  float* __restrict__ out, bf* __restrict__ ohi, bf* __restrict__ olo)
{
  int n=blockIdx.x;
  const float* a = Xa + (size_t)n*Dz;
  const float* c = Xb + (size_t)n*Dz;
  int tid=threadIdx.x, lane=tid&31, w=tid>>5;
  __shared__ float sh[8];
  float s0=a[tid]+c[tid], s1=a[tid+256]+c[tid+256];
  float sum=s0+s1;
  #pragma unroll
  for(int o=16;o;o>>=1) sum+=__shfl_xor_sync(0xffffffffu,sum,o);
  if(lane==0) sh[w]=sum;
  __syncthreads();
  float tot=0.f;
  #pragma unroll
  for(int i=0;i<8;i++) tot+=sh[i];
  __syncthreads();
  float mean=tot*(1.0f/(float)Dz);
  float d0=s0-mean, d1=s1-mean;
  float ss=d0*d0+d1*d1;
  #pragma unroll
  for(int o=16;o;o>>=1) ss+=__shfl_xor_sync(0xffffffffu,ss,o);
  if(lane==0) sh[w]=ss;
  __syncthreads();
  float tot2=0.f;
  #pragma unroll
  for(int i=0;i<8;i++) tot2+=sh[i];
  float var=tot2*(1.0f/(float)(Dz-1));
  float r=1.0f/(sqrtf(var)+1e-6f);
  float v0=g[tid]*d0*r+be[tid];
  float v1=g[tid+256]*d1*r+be[tid+256];
  size_t o0=(size_t)n*Dz+tid, o1=o0+256;
  out[o0]=v0; out[o1]=v1;
  if (SPLIT){
    bf h,l;
    split_bf(v0,h,l); ohi[o0]=h; olo[o0]=l;
    split_bf(v1,h,l); ohi[o1]=h; olo[o1]=l;
  }
}

extern "C" void kernel_launch(void* const* d_in, const int* in_sizes, int n_in,
                              void* d_out, int out_size)
{
  const float* x  =(const float*)d_in[0];
  const int* lens =(const int*)d_in[1];
  const float* Wq =(const float*)d_in[2];  const float* bq =(const float*)d_in[3];
  const float* Wk =(const float*)d_in[4];  const float* bk =(const float*)d_in[5];
  const float* Wv =(const float*)d_in[6];  const float* bv =(const float*)d_in[7];
  const float* Wo =(const float*)d_in[8];  const float* bo =(const float*)d_in[9];
  const float* W1 =(const float*)d_in[10]; const float* b1 =(const float*)d_in[11];
  const float* W2 =(const float*)d_in[12]; const float* b2 =(const float*)d_in[13];
  const float* g1 =(const float*)d_in[14]; const float* be1=(const float*)d_in[15];
  const float* g2 =(const float*)d_in[16]; const float* be2=(const float*)d_in[17];

  float* sc=nullptr;
  cudaGetSymbolAddress((void**)&sc, g_scratch);
  float *xb=sc+XBUF, *tb=sc+TBUF, *yb=sc+YBUF;
  bf *qhi=(bf*)(sc+QHIo), *qlo=(bf*)(sc+QLOo);
  bf *khi=(bf*)(sc+KHIo), *klo=(bf*)(sc+KLOo);
  bf *vthi=(bf*)(sc+VTHIo), *vtlo=(bf*)(sc+VTLOo);
  bf *abhi=(bf*)(sc+ABHIo), *ablo=(bf*)(sc+ABLOo);
  bf *xhi=(bf*)(sc+XHIo), *xlo=(bf*)(sc+XLOo);
  bf *yhi=(bf*)(sc+YHIo), *ylo=(bf*)(sc+YLOo);
  bf *fhi=(bf*)(sc+FHIo), *flo=(bf*)(sc+FLOo);
  bf *wqh=(bf*)(sc+WQo), *wql=wqh+WPROJ;
  bf *wkh=(bf*)(sc+WKo), *wkl=wkh+WPROJ;
  bf *wvh=(bf*)(sc+WVo), *wvl=wvh+WPROJ;
  bf *woh=(bf*)(sc+WOo), *wol=woh+WPROJ;
  bf *w1h=(bf*)(sc+W1o), *w1l=w1h+WFF;
  bf *w2h=(bf*)(sc+W2o), *w2l=w2h+WFF;

  cudaFuncSetAttribute(gemm_mma_kernel<0>, cudaFuncAttributeMaxDynamicSharedMemorySize, GEMM_SMEM);
  cudaFuncSetAttribute(gemm_mma_kernel<1>, cudaFuncAttributeMaxDynamicSharedMemorySize, GEMM_SMEM);
  cudaFuncSetAttribute(gemm_mma_kernel<2>, cudaFuncAttributeMaxDynamicSharedMemorySize, GEMM_SMEM);
  cudaFuncSetAttribute(gemm_mma_kernel<3>, cudaFuncAttributeMaxDynamicSharedMemorySize, GEMM_SMEM);
  cudaFuncSetAttribute(flash_kernel, cudaFuncAttributeMaxDynamicSharedMemorySize, FLASH_SMEM);

  dim3 wb(32,8);
  wsplit_kernel<<<dim3(Dz/32,Dz/32,Lz), wb>>>(Wq, wqh, wql, Dz, Dz);
  wsplit_kernel<<<dim3(Dz/32,Dz/32,Lz), wb>>>(Wk, wkh, wkl, Dz, Dz);
  wsplit_kernel<<<dim3(Dz/32,Dz/32,Lz), wb>>>(Wv, wvh, wvl, Dz, Dz);
  wsplit_kernel<<<dim3(Dz/32,Dz/32,Lz), wb>>>(Wo, woh, wol, Dz, Dz);
  wsplit_kernel<<<dim3(FFz/32,Dz/32,Lz), wb>>>(W1, w1h, w1l, Dz, FFz);
  wsplit_kernel<<<dim3(Dz/32,FFz/32,Lz), wb>>>(W2, w2h, w2l, FFz, Dz);

  posenc_kernel<<<(Nz*Dz)/256, 256>>>(x, xb, xhi, xlo);

  dim3 gproj(Dz/128, Nz/128);
  dim3 gff1(FFz/128, Nz/128);

  for (int l=0;l<Lz;l++){
    size_t wp=(size_t)l*Dz*Dz, wf=(size_t)l*Dz*FFz;
    gemm_mma_kernel<2><<<gproj,256,GEMM_SMEM>>>(xhi,xlo, wqh+wp,wql+wp, bq+l*Dz, nullptr,qhi,qlo, Dz,Dz);
    gemm_mma_kernel<2><<<gproj,256,GEMM_SMEM>>>(xhi,xlo, wkh+wp,wkl+wp, bk+l*Dz, nullptr,khi,klo, Dz,Dz);
    gemm_mma_kernel<3><<<gproj,256,GEMM_SMEM>>>(xhi,xlo, wvh+wp,wvl+wp, bv+l*Dz, nullptr,vthi,vtlo, Dz,Dz);

    flash_kernel<<<dim3(Sz/128, Bz*Hz),256,FLASH_SMEM>>>(qhi,qlo,khi,klo,vthi,vtlo,lens,abhi,ablo);

    gemm_mma_kernel<0><<<gproj,256,GEMM_SMEM>>>(abhi,ablo, woh+wp,wol+wp, bo+l*Dz, tb,nullptr,nullptr, Dz,Dz);
    ln_kernel<true><<<Nz,256>>>(xb,tb,g1+l*Dz,be1+l*Dz, yb,yhi,ylo);

    gemm_mma_kernel<1><<<gff1,256,GEMM_SMEM>>>(yhi,ylo, w1h+wf,w1l+wf, b1+(size_t)l*FFz, nullptr,fhi,flo, Dz,FFz);
    gemm_mma_kernel<0><<<gproj,256,GEMM_SMEM>>>(fhi,flo, w2h+wf,w2l+wf, b2+l*Dz, tb,nullptr,nullptr, FFz,Dz);

    if (l==Lz-1)
      ln_kernel<false><<<Nz,256>>>(yb,tb,g2+l*Dz,be2+l*Dz,(float*)d_out,nullptr,nullptr);
    else
      ln_kernel<true><<<Nz,256>>>(yb,tb,g2+l*Dz,be2+l*Dz, xb,xhi,xlo);
  }
}